// round 1
// baseline (speedup 1.0000x reference)
#include <cuda_runtime.h>
#include <math.h>

// =====================================================================
// NN_Model_19748259627524 — Bayesian NN sampling forward pass.
//   x:     (16384, 17) fp32
//   ms_vs: (2306,)     fp32  [m_w0(1088) | m_pri(65) | v_w0raw(1088) | v_priraw(65)]
// out = [pred(16384*100*100) | m_w0(1088) | v_w0(1088) | m_pri(65) | v_pri(65)]
// =====================================================================

// JAX >= 0.4.36 defaults jax_threefry_partitionable=True. Flip to 0 if
// rel_err comes back O(1) (RNG-variant mismatch signal).
#define JAX_PARTITIONABLE 1

#define K_N     16384
#define K_D     17
#define K_H     64
#define K_M     100
#define K_LENM  1088
#define K_MPRI  65
#define PRED_ELEMS 163840000LL   // 16384*100*100

// scratch: sampled weights
__device__ float g_w0[K_M * K_LENM];   // [m][i], i = d*64+h
__device__ float g_w1[K_MPRI * K_M];   // [d][c]

// ---------------------------------------------------------------------
// threefry2x32 (JAX rotation schedule, 20 rounds)
// ---------------------------------------------------------------------
__device__ __forceinline__ void tf2x32(unsigned k0, unsigned k1,
                                       unsigned x0, unsigned x1,
                                       unsigned &o0, unsigned &o1) {
  unsigned ks2 = k0 ^ k1 ^ 0x1BD11BDAu;
  x0 += k0; x1 += k1;
#define TF_R(r) { x0 += x1; x1 = (x1 << (r)) | (x1 >> (32 - (r))); x1 ^= x0; }
  TF_R(13) TF_R(15) TF_R(26) TF_R(6)  x0 += k1;  x1 += ks2 + 1u;
  TF_R(17) TF_R(29) TF_R(16) TF_R(24) x0 += ks2; x1 += k0 + 2u;
  TF_R(13) TF_R(15) TF_R(26) TF_R(6)  x0 += k0;  x1 += k1 + 3u;
  TF_R(17) TF_R(29) TF_R(16) TF_R(24) x0 += k1;  x1 += ks2 + 4u;
  TF_R(13) TF_R(15) TF_R(26) TF_R(6)  x0 += ks2; x1 += k0 + 5u;
#undef TF_R
  o0 = x0; o1 = x1;
}

// subkeys of jax.random.split(jax.random.key(42))
__device__ __forceinline__ void get_key(unsigned which, unsigned &s0, unsigned &s1) {
#if JAX_PARTITIONABLE
  // foldlike split: subkey_j = threefry(key, hi=0, lo=j), both lanes
  tf2x32(0u, 42u, 0u, which, s0, s1);
#else
  // original split: bits = threefry(key, iota(4)) pairs (0,2),(1,3)
  unsigned a0, a1, b0, b1;
  tf2x32(0u, 42u, 0u, 2u, a0, a1);
  tf2x32(0u, 42u, 1u, 3u, b0, b1);
  if (which == 0u) { s0 = a0; s1 = b0; } else { s0 = a1; s1 = b1; }
#endif
}

// jax.random.normal element idx of a flat array of size 2*half
__device__ __forceinline__ float jax_normal(unsigned k0, unsigned k1,
                                            unsigned idx, unsigned half) {
  unsigned a, b, bits;
#if JAX_PARTITIONABLE
  tf2x32(k0, k1, 0u, idx, a, b);   // 64-bit counter: hi=0, lo=idx
  bits = a ^ b;
#else
  if (idx < half) { tf2x32(k0, k1, idx, idx + half, a, b); bits = a; }
  else            { tf2x32(k0, k1, idx - half, idx, a, b); bits = b; }
#endif
  // uniform in [lo, 1) with lo = nextafter(-1,0); then sqrt(2)*erfinv
  float u = __uint_as_float((bits >> 9) | 0x3f800000u) - 1.0f;
  float v = fmaf(u, 1.99999994f, -0.99999994f);
  v = fmaxf(v, -0.99999994f);
  return 1.41421356237f * erfinvf(v);
}

// ---------------------------------------------------------------------
// setup kernels: sample W0 (1088x100) and W1 (65x100), write param tails
// ---------------------------------------------------------------------
__global__ void setup_w0_kernel(const float* __restrict__ ms) {
  int j = blockIdx.x * blockDim.x + threadIdx.x;
  if (j >= K_LENM * K_M) return;
  unsigned s0, s1; get_key(0u, s0, s1);
  float eps = jax_normal(s0, s1, (unsigned)j, 54400u);
  int i = j / K_M;
  int m = j - i * K_M;
  float vv = fabsf(ms[1153 + i]) + 1e-6f;          // v_w0
  g_w0[m * K_LENM + i] = fmaf(eps, sqrtf(vv), ms[i]);
}

__global__ void setup_w1_tail_kernel(const float* __restrict__ ms,
                                     float* __restrict__ out, int out_size) {
  int j = blockIdx.x * blockDim.x + threadIdx.x;
  if (j < K_MPRI * K_M) {
    unsigned s0, s1; get_key(1u, s0, s1);
    float eps = jax_normal(s0, s1, (unsigned)j, 3250u);
    int d = j / K_M;
    float vv = fabsf(ms[2241 + d]) + 1e-6f;        // v_pri
    g_w1[j] = fmaf(eps, sqrtf(vv), ms[1088 + d]);  // m_pri
  }
  if ((long long)out_size >= PRED_ELEMS + 2306LL) {
    size_t P = (size_t)PRED_ELEMS;
    if (j < 1088) {
      out[P + j]        = ms[j];                       // m_w0
      out[P + 1088 + j] = fabsf(ms[1153 + j]) + 1e-6f; // v_w0
    }
    if (j < 65) {
      out[P + 2176 + j] = ms[1088 + j];                // m_pri
      out[P + 2241 + j] = fabsf(ms[2241 + j]) + 1e-6f; // v_pri
    }
  }
}

// ---------------------------------------------------------------------
// f32x2 packed-FMA helpers (FFMA2: PTX-only, 2x fp32 MAC rate on sm_103a)
// ---------------------------------------------------------------------
__device__ __forceinline__ unsigned long long pack2(float a, float b) {
  unsigned long long r;
  asm("mov.b64 %0, {%1,%2};" : "=l"(r) : "f"(a), "f"(b));
  return r;
}
__device__ __forceinline__ unsigned long long fma2(unsigned long long a,
                                                   unsigned long long b,
                                                   unsigned long long c) {
  unsigned long long d;
  asm("fma.rn.f32x2 %0, %1, %2, %3;" : "=l"(d) : "l"(a), "l"(b), "l"(c));
  return d;
}
__device__ __forceinline__ float2 unpack2(unsigned long long v) {
  float2 r;
  asm("mov.b64 {%0,%1}, %2;" : "=f"(r.x), "=f"(r.y) : "l"(v));
  return r;
}

// ---------------------------------------------------------------------
// main fused kernel:
//   grid = (512 n-tiles of 32, 4 m-chunks of 25), 128 threads
//   per m: stage1 z[64h][32n] in smem; stage2 (32n x 128c) reg-tiled 4x8
// ---------------------------------------------------------------------
__global__ void __launch_bounds__(128)
pred_kernel(const float* __restrict__ x, float* __restrict__ out) {
  __shared__ __align__(16) float w1p[64 * 128];   // [h][c], c zero-padded to 128
  __shared__ __align__(16) float s_bias[128];     // W1 row 0
  __shared__ __align__(16) float xs[32 * 18];     // [n][d], stride-18 pad
  __shared__ __align__(16) float w0s[K_LENM];     // W0 slice for current m
  __shared__ __align__(16) float zs[64 * 32];     // [h][n]

  const int tid = threadIdx.x;
  const int n0 = blockIdx.x * 32;
  const int mbase = blockIdx.y * 25;

  // --- per-block staging ---
  for (int idx = tid; idx < 64 * 128; idx += 128) {
    int h = idx >> 7, c = idx & 127;
    w1p[idx] = (c < K_M) ? g_w1[(h + 1) * K_M + c] : 0.0f;
  }
  s_bias[tid] = (tid < K_M) ? g_w1[tid] : 0.0f;
  for (int idx = tid; idx < 32 * K_D; idx += 128) {
    int n = idx / K_D, d = idx - n * K_D;
    xs[n * 18 + d] = x[(size_t)(n0 + n) * K_D + d];
  }
  __syncthreads();

  // stage-1 thread mapping: 2 n's x 8 h's per thread
  const int tn2 = (tid & 15) * 2;
  const int hbase = (tid >> 4) * 8;
  float xr0[K_D], xr1[K_D];
#pragma unroll
  for (int d = 0; d < K_D; ++d) {
    xr0[d] = xs[tn2 * 18 + d];
    xr1[d] = xs[tn2 * 18 + 18 + d];
  }

  // stage-2 thread mapping: 4 n's (ng*4..) x 8 c's (cg*8..) per thread
  const int cg = tid & 15;
  const int ng = tid >> 4;

  ulonglong2 b01 = *(const ulonglong2*)&s_bias[cg * 8];
  ulonglong2 b23 = *(const ulonglong2*)&s_bias[cg * 8 + 4];

  for (int mi = 0; mi < 25; ++mi) {
    const int m = mbase + mi;

    // load W0 slice for this m (coalesced; L2-resident across blocks)
    for (int idx = tid; idx < K_LENM; idx += 128)
      w0s[idx] = g_w0[m * K_LENM + idx];
    __syncthreads();

    // ---- stage 1: z[h][n] = relu(x . W0[:,h,m]) ----
#pragma unroll
    for (int i = 0; i < 8; ++i) {
      float a0 = 0.0f, a1 = 0.0f;
#pragma unroll
      for (int d = 0; d < K_D; ++d) {
        float w = w0s[d * 64 + hbase + i];
        a0 = fmaf(xr0[d], w, a0);
        a1 = fmaf(xr1[d], w, a1);
      }
      *(float2*)&zs[(hbase + i) * 32 + tn2] =
          make_float2(fmaxf(a0, 0.0f), fmaxf(a1, 0.0f));
    }
    __syncthreads();

    // ---- stage 2: pred[n,m,c] = bias[c] + sum_h z[h][n]*w1p[h][c] ----
    unsigned long long acc[4][4];
#pragma unroll
    for (int i = 0; i < 4; ++i) {
      acc[i][0] = b01.x; acc[i][1] = b01.y;
      acc[i][2] = b23.x; acc[i][3] = b23.y;
    }

#pragma unroll 2
    for (int h = 0; h < 64; ++h) {
      float4 zv = *(const float4*)&zs[h * 32 + ng * 4];
      ulonglong2 w01 = *(const ulonglong2*)&w1p[h * 128 + cg * 8];
      ulonglong2 w23 = *(const ulonglong2*)&w1p[h * 128 + cg * 8 + 4];
      unsigned long long zp0 = pack2(zv.x, zv.x);
      unsigned long long zp1 = pack2(zv.y, zv.y);
      unsigned long long zp2 = pack2(zv.z, zv.z);
      unsigned long long zp3 = pack2(zv.w, zv.w);
      acc[0][0] = fma2(zp0, w01.x, acc[0][0]);
      acc[0][1] = fma2(zp0, w01.y, acc[0][1]);
      acc[0][2] = fma2(zp0, w23.x, acc[0][2]);
      acc[0][3] = fma2(zp0, w23.y, acc[0][3]);
      acc[1][0] = fma2(zp1, w01.x, acc[1][0]);
      acc[1][1] = fma2(zp1, w01.y, acc[1][1]);
      acc[1][2] = fma2(zp1, w23.x, acc[1][2]);
      acc[1][3] = fma2(zp1, w23.y, acc[1][3]);
      acc[2][0] = fma2(zp2, w01.x, acc[2][0]);
      acc[2][1] = fma2(zp2, w01.y, acc[2][1]);
      acc[2][2] = fma2(zp2, w23.x, acc[2][2]);
      acc[2][3] = fma2(zp2, w23.y, acc[2][3]);
      acc[3][0] = fma2(zp3, w01.x, acc[3][0]);
      acc[3][1] = fma2(zp3, w01.y, acc[3][1]);
      acc[3][2] = fma2(zp3, w23.x, acc[3][2]);
      acc[3][3] = fma2(zp3, w23.y, acc[3][3]);
    }

    // ---- store: only c < 100 is real output ----
    if (cg < 13) {
#pragma unroll
      for (int i = 0; i < 4; ++i) {
        size_t n = (size_t)(n0 + ng * 4 + i);
        float* p = out + n * 10000u + (unsigned)m * 100u + cg * 8;
        float2 f0 = unpack2(acc[i][0]);
        float2 f1 = unpack2(acc[i][1]);
        *(float4*)p = make_float4(f0.x, f0.y, f1.x, f1.y);
        if (cg < 12) {
          float2 f2 = unpack2(acc[i][2]);
          float2 f3 = unpack2(acc[i][3]);
          *(float4*)(p + 4) = make_float4(f2.x, f2.y, f3.x, f3.y);
        }
      }
    }
    __syncthreads();
  }
}

// ---------------------------------------------------------------------
extern "C" void kernel_launch(void* const* d_in, const int* in_sizes, int n_in,
                              void* d_out, int out_size) {
  const float* x  = (const float*)d_in[0];
  const float* ms = (const float*)d_in[1];
  if (n_in >= 2 && in_sizes[0] == 2306) {  // defensive input-order swap
    x  = (const float*)d_in[1];
    ms = (const float*)d_in[0];
  }
  float* out = (float*)d_out;

  setup_w0_kernel<<<(K_LENM * K_M + 255) / 256, 256>>>(ms);
  setup_w1_tail_kernel<<<32, 256>>>(ms, out, out_size);

  dim3 grid(K_N / 32, 4);
  pred_kernel<<<grid, 128>>>(x, out);
}

// round 7
// speedup vs baseline: 2.2432x; 2.2432x over previous
#include <cuda_runtime.h>
#include <cuda_bf16.h>
#include <cstdint>
#include <math.h>

// =====================================================================
// NN_Model_19748259627524 — Bayesian NN sampling forward pass.
//   x:     (16384, 17) fp32
//   ms_vs: (2306,)     fp32  [m_w0(1088) | m_pri(65) | v_w0raw(1088) | v_priraw(65)]
// out = [pred(16384*100*100) | m_w0(1088) | v_w0(1088) | m_pri(65) | v_pri(65)]
//
// Stage-1 (z = relu(x@W0_m)) scalar fp32 (exact).
// Stage-2 (pred = z@W1 + bias) via mma.sync bf16 (HMMA) with 3-term hi/lo
// split: zh*Wh + zl*Wh + zh*Wl  (dropped zl*Wl term ~2^-16 relative).
// NOTE: tcgen05 unavailable — harness compiles PTX for generic sm_103.
// R6 fix: missing __syncthreads() before bias broadcast read (race).
// =====================================================================

#define JAX_PARTITIONABLE 1

#define K_N     16384
#define K_D     17
#define K_H     64
#define K_M     100
#define K_LENM  1088
#define K_MPRI  65
#define PRED_ELEMS 163840000LL   // 16384*100*100

__device__ float g_w0[K_M * K_LENM];   // [m][i], i = d*64+h
__device__ float g_w1[K_MPRI * K_M];   // [d][c]

// ---------------------------------------------------------------------
// threefry2x32 (JAX rotation schedule)
// ---------------------------------------------------------------------
__device__ __forceinline__ void tf2x32(unsigned k0, unsigned k1,
                                       unsigned x0, unsigned x1,
                                       unsigned &o0, unsigned &o1) {
  unsigned ks2 = k0 ^ k1 ^ 0x1BD11BDAu;
  x0 += k0; x1 += k1;
#define TF_R(r) { x0 += x1; x1 = (x1 << (r)) | (x1 >> (32 - (r))); x1 ^= x0; }
  TF_R(13) TF_R(15) TF_R(26) TF_R(6)  x0 += k1;  x1 += ks2 + 1u;
  TF_R(17) TF_R(29) TF_R(16) TF_R(24) x0 += ks2; x1 += k0 + 2u;
  TF_R(13) TF_R(15) TF_R(26) TF_R(6)  x0 += k0;  x1 += k1 + 3u;
  TF_R(17) TF_R(29) TF_R(16) TF_R(24) x0 += k1;  x1 += ks2 + 4u;
  TF_R(13) TF_R(15) TF_R(26) TF_R(6)  x0 += ks2; x1 += k0 + 5u;
#undef TF_R
  o0 = x0; o1 = x1;
}

__device__ __forceinline__ void get_key(unsigned which, unsigned &s0, unsigned &s1) {
#if JAX_PARTITIONABLE
  tf2x32(0u, 42u, 0u, which, s0, s1);
#else
  unsigned a0, a1, b0, b1;
  tf2x32(0u, 42u, 0u, 2u, a0, a1);
  tf2x32(0u, 42u, 1u, 3u, b0, b1);
  if (which == 0u) { s0 = a0; s1 = b0; } else { s0 = a1; s1 = b1; }
#endif
}

__device__ __forceinline__ float jax_normal(unsigned k0, unsigned k1,
                                            unsigned idx, unsigned half) {
  unsigned a, b, bits;
#if JAX_PARTITIONABLE
  tf2x32(k0, k1, 0u, idx, a, b);
  bits = a ^ b;
#else
  if (idx < half) { tf2x32(k0, k1, idx, idx + half, a, b); bits = a; }
  else            { tf2x32(k0, k1, idx - half, idx, a, b); bits = b; }
#endif
  float u = __uint_as_float((bits >> 9) | 0x3f800000u) - 1.0f;
  float v = fmaf(u, 1.99999994f, -0.99999994f);
  v = fmaxf(v, -0.99999994f);
  return 1.41421356237f * erfinvf(v);
}

// ---------------------------------------------------------------------
// setup kernels
// ---------------------------------------------------------------------
__global__ void setup_w0_kernel(const float* __restrict__ ms) {
  int j = blockIdx.x * blockDim.x + threadIdx.x;
  if (j >= K_LENM * K_M) return;
  unsigned s0, s1; get_key(0u, s0, s1);
  float eps = jax_normal(s0, s1, (unsigned)j, 54400u);
  int i = j / K_M;
  int m = j - i * K_M;
  float vv = fabsf(ms[1153 + i]) + 1e-6f;
  g_w0[m * K_LENM + i] = fmaf(eps, sqrtf(vv), ms[i]);
}

__global__ void setup_w1_tail_kernel(const float* __restrict__ ms,
                                     float* __restrict__ out, int out_size) {
  int j = blockIdx.x * blockDim.x + threadIdx.x;
  if (j < K_MPRI * K_M) {
    unsigned s0, s1; get_key(1u, s0, s1);
    float eps = jax_normal(s0, s1, (unsigned)j, 3250u);
    int d = j / K_M;
    float vv = fabsf(ms[2241 + d]) + 1e-6f;
    g_w1[j] = fmaf(eps, sqrtf(vv), ms[1088 + d]);
  }
  if ((long long)out_size >= PRED_ELEMS + 2306LL) {
    size_t P = (size_t)PRED_ELEMS;
    if (j < 1088) {
      out[P + j]        = ms[j];
      out[P + 1088 + j] = fabsf(ms[1153 + j]) + 1e-6f;
    }
    if (j < 65) {
      out[P + 2176 + j] = ms[1088 + j];
      out[P + 2241 + j] = fabsf(ms[2241 + j]) + 1e-6f;
    }
  }
}

// ---------------------------------------------------------------------
// warp-MMA helpers (sm_80+ baseline; works on generic sm_103 target)
// ---------------------------------------------------------------------
__device__ __forceinline__ uint32_t smem_u32(const void* p) {
  uint32_t a;
  asm("{ .reg .u64 t; cvta.to.shared.u64 t, %1; cvt.u32.u64 %0, t; }"
      : "=r"(a) : "l"(p));
  return a;
}

__device__ __forceinline__ void ldsm_x4(uint32_t &r0, uint32_t &r1,
                                        uint32_t &r2, uint32_t &r3,
                                        uint32_t addr) {
  asm volatile("ldmatrix.sync.aligned.m8n8.x4.shared.b16 {%0,%1,%2,%3}, [%4];"
               : "=r"(r0), "=r"(r1), "=r"(r2), "=r"(r3) : "r"(addr));
}

__device__ __forceinline__ void mma_bf16(float &c0, float &c1, float &c2, float &c3,
                                         uint32_t a0, uint32_t a1, uint32_t a2, uint32_t a3,
                                         uint32_t b0, uint32_t b1) {
  asm volatile(
      "mma.sync.aligned.m16n8k16.row.col.f32.bf16.bf16.f32 "
      "{%0,%1,%2,%3}, {%4,%5,%6,%7}, {%8,%9}, {%0,%1,%2,%3};"
      : "+f"(c0), "+f"(c1), "+f"(c2), "+f"(c3)
      : "r"(a0), "r"(a1), "r"(a2), "r"(a3), "r"(b0), "r"(b1));
}

// ---------------------------------------------------------------------
// fused pred kernel
//   grid = (128 n-tiles of 128, 4 m-chunks of 25), 256 threads (8 warps)
//   A' smem: [128 n][128 k bf16]  k 0-63 = zh(h), 64-127 = zl(h)
//   B' smem: [112 c][128 k bf16]  k 0-63 = W1h(h), 64-127 = W1l(h)
//   row stride 272 bytes (136 bf16): 16B-aligned
// ---------------------------------------------------------------------
#define ASTRIDE 272
#define SM_A    0          // 128*272 = 34816
#define SM_B    34816      // 112*272 = 30464
#define SM_XT   65280      // 17*128*4 = 8704
#define SM_W0   73984      // 1088*4 = 4352
#define SM_BIAS 78336      // 128*4 = 512
#define SM_TOTAL 78848

// (A k-pair, B k-pair) groups realizing the 3 split terms; each pair = 2 k16 steps
__constant__ int g_akp[6] = {0, 1, 2, 3, 0, 1};  // A k-step pair idx
__constant__ int g_bkp[6] = {0, 1, 0, 1, 2, 3};  // B k-step pair idx

__global__ void __launch_bounds__(256, 2)
pred_kernel(const float* __restrict__ x, float* __restrict__ out) {
  extern __shared__ char smem[];
  const uint32_t sbase = smem_u32(smem);
  float* xT     = (float*)(smem + SM_XT);
  float* w0s    = (float*)(smem + SM_W0);
  float* bias_s = (float*)(smem + SM_BIAS);

  const int tid  = threadIdx.x;
  const int wid  = tid >> 5;
  const int lane = tid & 31;
  const int n0 = blockIdx.x * 128;
  const int mbase = blockIdx.y * 25;

  // ---- stage x transpose: xT[d][n] ----
  for (int idx = tid; idx < 128 * K_D; idx += 256) {
    int n = idx / K_D, d = idx - n * K_D;
    xT[d * 128 + n] = x[(size_t)n0 * K_D + idx];
  }

  // ---- build B' = [W1h | W1l] rows c (zero-pad c>=100), and bias ----
  for (int idx = tid; idx < 112 * 32; idx += 256) {
    int c = idx >> 5;
    int h0 = (idx & 31) * 2;
    float v0 = (c < K_M) ? g_w1[(h0 + 1) * K_M + c] : 0.0f;
    float v1 = (c < K_M) ? g_w1[(h0 + 2) * K_M + c] : 0.0f;
    __nv_bfloat162 h2, l2;
    h2.x = __float2bfloat16(v0);
    h2.y = __float2bfloat16(v1);
    l2.x = __float2bfloat16(v0 - __bfloat162float(h2.x));
    l2.y = __float2bfloat16(v1 - __bfloat162float(h2.y));
    char* row = smem + SM_B + c * ASTRIDE;
    *(__nv_bfloat162*)(row + h0 * 2)         = h2;
    *(__nv_bfloat162*)(row + 128 + h0 * 2)   = l2;
  }
  if (tid < 128) bias_s[tid] = (tid < K_M) ? g_w1[tid] : 0.0f;

  __syncthreads();   // R6 FIX: bias_s/xT/B' visible before cross-thread reads

  // stage-1 mapping: 8 h per warp (ht), 4 n per thread (lane + 32i)
  const int ht = wid * 8;

  // stage-2 mapping: warp (wr, wc): rows wr*32 (2 m16 tiles), cols wc*56
  const int wr = wid >> 1;
  const int wc = wid & 1;
  const int cbase = wc * 56;
  const int nct = wc ? 6 : 7;          // c-tiles (c>=104 unused)
  const int trow = lane >> 2;          // 0..7
  const int tcol = (lane & 3) * 2;     // 0,2,4,6

  // per-thread bias for each c-tile
  float2 biasv[7];
#pragma unroll
  for (int j = 0; j < 7; ++j) {
    int c = cbase + j * 8 + tcol;
    biasv[j] = make_float2(bias_s[c], bias_s[c + 1]);
  }

  for (int mi = 0; mi < 25; ++mi) {
    const int m = mbase + mi;

    __syncthreads();   // A'/w0s consumers from previous iter done
    for (int idx = tid; idx < K_LENM; idx += 256)
      w0s[idx] = g_w0[m * K_LENM + idx];
    __syncthreads();

    // ---- stage 1: z = relu(x @ W0_m); split to bf16 hi/lo into A' ----
    {
      float za[4][8];
#pragma unroll
      for (int i = 0; i < 4; ++i)
#pragma unroll
        for (int j = 0; j < 8; ++j) za[i][j] = 0.0f;

#pragma unroll
      for (int d = 0; d < K_D; ++d) {
        float xv[4];
#pragma unroll
        for (int i = 0; i < 4; ++i) xv[i] = xT[d * 128 + lane + 32 * i];
        float wv[8];
#pragma unroll
        for (int j = 0; j < 8; ++j) wv[j] = w0s[d * 64 + ht + j];
#pragma unroll
        for (int i = 0; i < 4; ++i)
#pragma unroll
          for (int j = 0; j < 8; ++j)
            za[i][j] = fmaf(xv[i], wv[j], za[i][j]);
      }

#pragma unroll
      for (int i = 0; i < 4; ++i) {
        char* row = smem + SM_A + (lane + 32 * i) * ASTRIDE;
#pragma unroll
        for (int jp = 0; jp < 4; ++jp) {
          float z0 = fmaxf(za[i][jp * 2], 0.0f);
          float z1 = fmaxf(za[i][jp * 2 + 1], 0.0f);
          __nv_bfloat162 h2, l2;
          h2.x = __float2bfloat16(z0);
          h2.y = __float2bfloat16(z1);
          l2.x = __float2bfloat16(z0 - __bfloat162float(h2.x));
          l2.y = __float2bfloat16(z1 - __bfloat162float(h2.y));
          int h0 = ht + jp * 2;
          *(__nv_bfloat162*)(row + h0 * 2)       = h2;
          *(__nv_bfloat162*)(row + 128 + h0 * 2) = l2;
        }
      }
    }
    __syncthreads();

    // ---- stage 2: warp MMA, acc init = bias ----
    float acc[2][7][4];
#pragma unroll
    for (int i = 0; i < 2; ++i)
#pragma unroll
      for (int j = 0; j < 7; ++j) {
        acc[i][j][0] = biasv[j].x; acc[i][j][1] = biasv[j].y;
        acc[i][j][2] = biasv[j].x; acc[i][j][3] = biasv[j].y;
      }

    const uint32_t a_lane_row = (uint32_t)(wr * 32 + (lane & 15));
    const uint32_t a_lane_k   = (uint32_t)((lane >> 4) * 8);
    const uint32_t b_lane_row = (uint32_t)(cbase + (lane & 7));
    const uint32_t b_lane_k   = (uint32_t)((lane >> 3) * 8);
    const uint32_t a_base = sbase + SM_A + a_lane_row * ASTRIDE + a_lane_k * 2;
    const uint32_t b_base = sbase + SM_B + b_lane_row * ASTRIDE + b_lane_k * 2;

#pragma unroll
    for (int g = 0; g < 6; ++g) {
      const int akp = g_akp[g];   // A k-steps 2*akp, 2*akp+1
      const int bkp = g_bkp[g];   // B k-steps 2*bkp, 2*bkp+1
      uint32_t af[2][2][4];
#pragma unroll
      for (int i = 0; i < 2; ++i)
#pragma unroll
        for (int s = 0; s < 2; ++s) {
          uint32_t addr = a_base + (uint32_t)(i * 16) * ASTRIDE +
                          (uint32_t)((akp * 2 + s) * 16) * 2;
          ldsm_x4(af[i][s][0], af[i][s][1], af[i][s][2], af[i][s][3], addr);
        }
#pragma unroll
      for (int j = 0; j < 7; ++j) {
        if (j >= nct) break;
        uint32_t bf[4];
        uint32_t addr = b_base + (uint32_t)(j * 8) * ASTRIDE +
                        (uint32_t)(bkp * 32) * 2;
        ldsm_x4(bf[0], bf[1], bf[2], bf[3], addr);
#pragma unroll
        for (int i = 0; i < 2; ++i) {
          mma_bf16(acc[i][j][0], acc[i][j][1], acc[i][j][2], acc[i][j][3],
                   af[i][0][0], af[i][0][1], af[i][0][2], af[i][0][3],
                   bf[0], bf[1]);
          mma_bf16(acc[i][j][0], acc[i][j][1], acc[i][j][2], acc[i][j][3],
                   af[i][1][0], af[i][1][1], af[i][1][2], af[i][1][3],
                   bf[2], bf[3]);
        }
      }
    }

    // ---- store (c<100 only) ----
#pragma unroll
    for (int i = 0; i < 2; ++i) {
      int nrow = n0 + wr * 32 + i * 16 + trow;
      float* p0 = out + (size_t)nrow * 10000u + (unsigned)m * 100u;
#pragma unroll
      for (int j = 0; j < 7; ++j) {
        if (j >= nct) break;
        int c = cbase + j * 8 + tcol;
        if (c < K_M) {
          *(float2*)(p0 + c) = make_float2(acc[i][j][0], acc[i][j][1]);
          *(float2*)(p0 + 8 * 10000u + c) =
              make_float2(acc[i][j][2], acc[i][j][3]);
        }
      }
    }
  }
}

// ---------------------------------------------------------------------
extern "C" void kernel_launch(void* const* d_in, const int* in_sizes, int n_in,
                              void* d_out, int out_size) {
  const float* x  = (const float*)d_in[0];
  const float* ms = (const float*)d_in[1];
  if (n_in >= 2 && in_sizes[0] == 2306) {
    x  = (const float*)d_in[1];
    ms = (const float*)d_in[0];
  }
  float* out = (float*)d_out;

  setup_w0_kernel<<<(K_LENM * K_M + 255) / 256, 256>>>(ms);
  setup_w1_tail_kernel<<<32, 256>>>(ms, out, out_size);

  cudaFuncSetAttribute(pred_kernel,
                       cudaFuncAttributeMaxDynamicSharedMemorySize, SM_TOTAL);
  dim3 grid(K_N / 128, 4);
  pred_kernel<<<grid, 256, SM_TOTAL>>>(x, out);
}

// round 10
// speedup vs baseline: 2.5776x; 1.1491x over previous
#include <cuda_runtime.h>
#include <cuda_bf16.h>
#include <cstdint>
#include <math.h>

// =====================================================================
// NN_Model_19748259627524 — Bayesian NN sampling forward pass.
// Stage-1 (z = relu(x@W0_m)) scalar fp32 (exact), software-pipelined and
// interleaved with Stage-2 (pred = z@W1 + bias) mma.sync bf16 (HMMA),
// 3-term hi/lo split: zh*Wh + zl*Wh + zh*Wl.
// R8: 2-barrier m-loop, w0 double-buffer + prefetch, stage1/stage2
//     instruction interleave, 2-pass c-split (register relief).
// =====================================================================

#define JAX_PARTITIONABLE 1

#define K_N     16384
#define K_D     17
#define K_H     64
#define K_M     100
#define K_LENM  1088
#define K_MPRI  65
#define PRED_ELEMS 163840000LL   // 16384*100*100

__device__ float g_w0[K_M * K_LENM];   // [m][i], i = d*64+h
__device__ float g_w1[K_MPRI * K_M];   // [d][c]

// ---------------------------------------------------------------------
// threefry2x32 (JAX rotation schedule)
// ---------------------------------------------------------------------
__device__ __forceinline__ void tf2x32(unsigned k0, unsigned k1,
                                       unsigned x0, unsigned x1,
                                       unsigned &o0, unsigned &o1) {
  unsigned ks2 = k0 ^ k1 ^ 0x1BD11BDAu;
  x0 += k0; x1 += k1;
#define TF_R(r) { x0 += x1; x1 = (x1 << (r)) | (x1 >> (32 - (r))); x1 ^= x0; }
  TF_R(13) TF_R(15) TF_R(26) TF_R(6)  x0 += k1;  x1 += ks2 + 1u;
  TF_R(17) TF_R(29) TF_R(16) TF_R(24) x0 += ks2; x1 += k0 + 2u;
  TF_R(13) TF_R(15) TF_R(26) TF_R(6)  x0 += k0;  x1 += k1 + 3u;
  TF_R(17) TF_R(29) TF_R(16) TF_R(24) x0 += k1;  x1 += ks2 + 4u;
  TF_R(13) TF_R(15) TF_R(26) TF_R(6)  x0 += ks2; x1 += k0 + 5u;
#undef TF_R
  o0 = x0; o1 = x1;
}

__device__ __forceinline__ void get_key(unsigned which, unsigned &s0, unsigned &s1) {
#if JAX_PARTITIONABLE
  tf2x32(0u, 42u, 0u, which, s0, s1);
#else
  unsigned a0, a1, b0, b1;
  tf2x32(0u, 42u, 0u, 2u, a0, a1);
  tf2x32(0u, 42u, 1u, 3u, b0, b1);
  if (which == 0u) { s0 = a0; s1 = b0; } else { s0 = a1; s1 = b1; }
#endif
}

__device__ __forceinline__ float jax_normal(unsigned k0, unsigned k1,
                                            unsigned idx, unsigned half) {
  unsigned a, b, bits;
#if JAX_PARTITIONABLE
  tf2x32(k0, k1, 0u, idx, a, b);
  bits = a ^ b;
#else
  if (idx < half) { tf2x32(k0, k1, idx, idx + half, a, b); bits = a; }
  else            { tf2x32(k0, k1, idx - half, idx, a, b); bits = b; }
#endif
  float u = __uint_as_float((bits >> 9) | 0x3f800000u) - 1.0f;
  float v = fmaf(u, 1.99999994f, -0.99999994f);
  v = fmaxf(v, -0.99999994f);
  return 1.41421356237f * erfinvf(v);
}

// ---------------------------------------------------------------------
// setup kernels
// ---------------------------------------------------------------------
__global__ void setup_w0_kernel(const float* __restrict__ ms) {
  int j = blockIdx.x * blockDim.x + threadIdx.x;
  if (j >= K_LENM * K_M) return;
  unsigned s0, s1; get_key(0u, s0, s1);
  float eps = jax_normal(s0, s1, (unsigned)j, 54400u);
  int i = j / K_M;
  int m = j - i * K_M;
  float vv = fabsf(ms[1153 + i]) + 1e-6f;
  g_w0[m * K_LENM + i] = fmaf(eps, sqrtf(vv), ms[i]);
}

__global__ void setup_w1_tail_kernel(const float* __restrict__ ms,
                                     float* __restrict__ out, int out_size) {
  int j = blockIdx.x * blockDim.x + threadIdx.x;
  if (j < K_MPRI * K_M) {
    unsigned s0, s1; get_key(1u, s0, s1);
    float eps = jax_normal(s0, s1, (unsigned)j, 3250u);
    int d = j / K_M;
    float vv = fabsf(ms[2241 + d]) + 1e-6f;
    g_w1[j] = fmaf(eps, sqrtf(vv), ms[1088 + d]);
  }
  if ((long long)out_size >= PRED_ELEMS + 2306LL) {
    size_t P = (size_t)PRED_ELEMS;
    if (j < 1088) {
      out[P + j]        = ms[j];
      out[P + 1088 + j] = fabsf(ms[1153 + j]) + 1e-6f;
    }
    if (j < 65) {
      out[P + 2176 + j] = ms[1088 + j];
      out[P + 2241 + j] = fabsf(ms[2241 + j]) + 1e-6f;
    }
  }
}

// ---------------------------------------------------------------------
// warp-MMA helpers
// ---------------------------------------------------------------------
__device__ __forceinline__ uint32_t smem_u32(const void* p) {
  uint32_t a;
  asm("{ .reg .u64 t; cvta.to.shared.u64 t, %1; cvt.u32.u64 %0, t; }"
      : "=r"(a) : "l"(p));
  return a;
}

__device__ __forceinline__ void ldsm_x4(uint32_t &r0, uint32_t &r1,
                                        uint32_t &r2, uint32_t &r3,
                                        uint32_t addr) {
  asm volatile("ldmatrix.sync.aligned.m8n8.x4.shared.b16 {%0,%1,%2,%3}, [%4];"
               : "=r"(r0), "=r"(r1), "=r"(r2), "=r"(r3) : "r"(addr));
}

__device__ __forceinline__ void mma_bf16(float &c0, float &c1, float &c2, float &c3,
                                         uint32_t a0, uint32_t a1, uint32_t a2, uint32_t a3,
                                         uint32_t b0, uint32_t b1) {
  asm volatile(
      "mma.sync.aligned.m16n8k16.row.col.f32.bf16.bf16.f32 "
      "{%0,%1,%2,%3}, {%4,%5,%6,%7}, {%8,%9}, {%0,%1,%2,%3};"
      : "+f"(c0), "+f"(c1), "+f"(c2), "+f"(c3)
      : "r"(a0), "r"(a1), "r"(a2), "r"(a3), "r"(b0), "r"(b1));
}

// ---------------------------------------------------------------------
// smem layout
// ---------------------------------------------------------------------
#define ASTRIDE 272
#define SM_A    0          // 128*272 = 34816
#define SM_B    34816      // 112*272 = 30464
#define SM_XT   65280      // 17*128*4 = 8704
#define SM_W0   73984      // 2 x 1088*4 = 8704 (double buffer)
#define SM_BIAS 82688      // 128*4 = 512
#define SM_TOTAL 83200

__constant__ int g_akp[6] = {0, 1, 2, 3, 0, 1};  // A k-step pair idx
__constant__ int g_bkp[6] = {0, 1, 0, 1, 2, 3};  // B k-step pair idx
// stage-1 d-step schedule across 12 group-slots: bounds floor(s*17/12)
__constant__ int g_dlo[13] = {0,1,2,4,5,7,8,9,11,12,14,15,17};

__global__ void __launch_bounds__(256, 2)
pred_kernel(const float* __restrict__ x, float* __restrict__ out) {
  extern __shared__ char smem[];
  const uint32_t sbase = smem_u32(smem);
  float* xT     = (float*)(smem + SM_XT);
  float* bias_s = (float*)(smem + SM_BIAS);

  const int tid  = threadIdx.x;
  const int wid  = tid >> 5;
  const int lane = tid & 31;
  const int n0 = blockIdx.x * 128;
  const int mbase = blockIdx.y * 25;

  // ---- stage xT[d][n] ----
  for (int idx = tid; idx < 128 * K_D; idx += 256) {
    int n = idx / K_D, d = idx - n * K_D;
    xT[d * 128 + n] = x[(size_t)n0 * K_D + idx];
  }

  // ---- build B' = [W1h | W1l] rows c (zero-pad c>=100), and bias ----
  for (int idx = tid; idx < 112 * 32; idx += 256) {
    int c = idx >> 5;
    int h0 = (idx & 31) * 2;
    float v0 = (c < K_M) ? g_w1[(h0 + 1) * K_M + c] : 0.0f;
    float v1 = (c < K_M) ? g_w1[(h0 + 2) * K_M + c] : 0.0f;
    __nv_bfloat162 h2, l2;
    h2.x = __float2bfloat16(v0);
    h2.y = __float2bfloat16(v1);
    l2.x = __float2bfloat16(v0 - __bfloat162float(h2.x));
    l2.y = __float2bfloat16(v1 - __bfloat162float(h2.y));
    char* row = smem + SM_B + c * ASTRIDE;
    *(__nv_bfloat162*)(row + h0 * 2)       = h2;
    *(__nv_bfloat162*)(row + 128 + h0 * 2) = l2;
  }
  if (tid < 128) bias_s[tid] = (tid < K_M) ? g_w1[tid] : 0.0f;

  // ---- prologue: w0(m0) -> buf0 ----
  {
    const float* src = g_w0 + (size_t)mbase * K_LENM;
    float* dst = (float*)(smem + SM_W0);
#pragma unroll
    for (int k = 0; k < 5; ++k) {
      int idx = tid + k * 256;
      if (idx < K_LENM) dst[idx] = src[idx];
    }
  }
  __syncthreads();

  const int ht = wid * 8;                       // stage-1 h base
  const int wr = wid >> 1;                      // stage-2 row warp
  const int wc = wid & 1;                       // stage-2 col warp
  const int cbase = wc * 56;
  const int nct = wc ? 6 : 7;
  const int trow = lane >> 2;
  const int tcol = (lane & 3) * 2;

  const uint32_t a_lane_row = (uint32_t)(wr * 32 + (lane & 15));
  const uint32_t a_lane_k   = (uint32_t)((lane >> 4) * 8);
  const uint32_t b_lane_row = (uint32_t)(cbase + (lane & 7));
  const uint32_t b_lane_k   = (uint32_t)((lane >> 3) * 8);
  const uint32_t a_base = sbase + SM_A + a_lane_row * ASTRIDE + a_lane_k * 2;
  const uint32_t b_base = sbase + SM_B + b_lane_row * ASTRIDE + b_lane_k * 2;

  // ---- prologue stage-1 for mi=0 ----
  float za[4][8];
#pragma unroll
  for (int i = 0; i < 4; ++i)
#pragma unroll
    for (int j = 0; j < 8; ++j) za[i][j] = 0.0f;
  {
    const float* w0s = (const float*)(smem + SM_W0);
#pragma unroll
    for (int d = 0; d < K_D; ++d) {
      float xv[4];
#pragma unroll
      for (int i = 0; i < 4; ++i) xv[i] = xT[d * 128 + lane + 32 * i];
      float wv[8];
#pragma unroll
      for (int j = 0; j < 8; ++j) wv[j] = w0s[d * 64 + ht + j];
#pragma unroll
      for (int i = 0; i < 4; ++i)
#pragma unroll
        for (int j = 0; j < 8; ++j)
          za[i][j] = fmaf(xv[i], wv[j], za[i][j]);
    }
  }

  // prefetch w0(m1) into regs
  float pf[5];
  {
    const float* src = g_w0 + (size_t)(mbase + 1) * K_LENM;
#pragma unroll
    for (int k = 0; k < 5; ++k) {
      int idx = tid + k * 256;
      pf[k] = (idx < K_LENM) ? src[idx] : 0.0f;
    }
  }

  for (int mi = 0; mi < 25; ++mi) {
    const int m = mbase + mi;

    // ======== phase A: publish A'(za), publish w0(m+1) ========
#pragma unroll
    for (int i = 0; i < 4; ++i) {
      char* row = smem + SM_A + (lane + 32 * i) * ASTRIDE;
#pragma unroll
      for (int jp = 0; jp < 4; ++jp) {
        float z0 = fmaxf(za[i][jp * 2], 0.0f);
        float z1 = fmaxf(za[i][jp * 2 + 1], 0.0f);
        __nv_bfloat162 h2, l2;
        h2.x = __float2bfloat16(z0);
        h2.y = __float2bfloat16(z1);
        l2.x = __float2bfloat16(z0 - __bfloat162float(h2.x));
        l2.y = __float2bfloat16(z1 - __bfloat162float(h2.y));
        int h0 = ht + jp * 2;
        *(__nv_bfloat162*)(row + h0 * 2)       = h2;
        *(__nv_bfloat162*)(row + 128 + h0 * 2) = l2;
      }
    }
    if (mi + 1 < 25) {
      float* dst = (float*)(smem + SM_W0 + ((mi + 1) & 1) * 4352);
#pragma unroll
      for (int k = 0; k < 5; ++k) {
        int idx = tid + k * 256;
        if (idx < K_LENM) dst[idx] = pf[k];
      }
    }
    __syncthreads();

    // ======== phase B: MMA(m) interleaved with stage-1(m+1) ========
    const int do_next = (mi + 1 < 25);
    const float* w0n = (const float*)(smem + SM_W0 + ((mi + 1) & 1) * 4352);

    // prefetch w0(m+2) into regs (long-latency LDG issued first)
    if (mi + 2 < 25) {
      const float* src = g_w0 + (size_t)(m + 2) * K_LENM;
#pragma unroll
      for (int k = 0; k < 5; ++k) {
        int idx = tid + k * 256;
        pf[k] = src[idx < K_LENM ? idx : 0];
      }
    }

    // zero za for m+1
#pragma unroll
    for (int i = 0; i < 4; ++i)
#pragma unroll
      for (int j = 0; j < 8; ++j) za[i][j] = 0.0f;

    // two c-passes: pass 0 -> tiles 0..3, pass 1 -> tiles 4..nct-1
#pragma unroll
    for (int pass = 0; pass < 2; ++pass) {
      const int jbase = pass ? 4 : 0;
      const int jcnt  = pass ? (nct - 4) : 4;
      float acc[2][4][4];
#pragma unroll
      for (int i = 0; i < 2; ++i)
#pragma unroll
        for (int j = 0; j < 4; ++j)
#pragma unroll
          for (int q = 0; q < 4; ++q) acc[i][j][q] = 0.0f;

#pragma unroll
      for (int g = 0; g < 6; ++g) {
        // ---- stage-1 d-step slice (slot s = pass*6 + g) ----
        {
          const int s = pass * 6 + g;
          const int dlo = g_dlo[s], dhi = g_dlo[s + 1];
          if (do_next) {
#pragma unroll
            for (int d = 0; d < 2; ++d) {
              int dd = dlo + d;
              if (dd < dhi) {
                float xv[4];
#pragma unroll
                for (int i = 0; i < 4; ++i) xv[i] = xT[dd * 128 + lane + 32 * i];
                float wv[8];
#pragma unroll
                for (int j = 0; j < 8; ++j) wv[j] = w0n[dd * 64 + ht + j];
#pragma unroll
                for (int i = 0; i < 4; ++i)
#pragma unroll
                  for (int j = 0; j < 8; ++j)
                    za[i][j] = fmaf(xv[i], wv[j], za[i][j]);
              }
            }
          }
        }
        // ---- MMA group g ----
        const int akp = g_akp[g];
        const int bkp = g_bkp[g];
        uint32_t af[2][2][4];
#pragma unroll
        for (int i = 0; i < 2; ++i)
#pragma unroll
          for (int s2 = 0; s2 < 2; ++s2) {
            uint32_t addr = a_base + (uint32_t)(i * 16) * ASTRIDE +
                            (uint32_t)((akp * 2 + s2) * 16) * 2;
            ldsm_x4(af[i][s2][0], af[i][s2][1], af[i][s2][2], af[i][s2][3], addr);
          }
#pragma unroll
        for (int j = 0; j < 4; ++j) {
          if (j >= jcnt) break;
          uint32_t bf[4];
          uint32_t addr = b_base + (uint32_t)((jbase + j) * 8) * ASTRIDE +
                          (uint32_t)(bkp * 32) * 2;
          ldsm_x4(bf[0], bf[1], bf[2], bf[3], addr);
#pragma unroll
          for (int i = 0; i < 2; ++i) {
            mma_bf16(acc[i][j][0], acc[i][j][1], acc[i][j][2], acc[i][j][3],
                     af[i][0][0], af[i][0][1], af[i][0][2], af[i][0][3],
                     bf[0], bf[1]);
            mma_bf16(acc[i][j][0], acc[i][j][1], acc[i][j][2], acc[i][j][3],
                     af[i][1][0], af[i][1][1], af[i][1][2], af[i][1][3],
                     bf[2], bf[3]);
          }
        }
      }

      // ---- store this pass (c<100 only), add bias from smem ----
#pragma unroll
      for (int i = 0; i < 2; ++i) {
        int nrow = n0 + wr * 32 + i * 16 + trow;
        float* p0 = out + (size_t)nrow * 10000u + (unsigned)m * 100u;
#pragma unroll
        for (int j = 0; j < 4; ++j) {
          if (j >= jcnt) break;
          int c = cbase + (jbase + j) * 8 + tcol;
          if (c < K_M) {
            float b0 = bias_s[c], b1 = bias_s[c + 1];
            *(float2*)(p0 + c) =
                make_float2(acc[i][j][0] + b0, acc[i][j][1] + b1);
            *(float2*)(p0 + 8 * 10000u + c) =
                make_float2(acc[i][j][2] + b0, acc[i][j][3] + b1);
          }
        }
      }
    }
    __syncthreads();   // A' & w0 buffers free for next phase A
  }
}

// ---------------------------------------------------------------------
extern "C" void kernel_launch(void* const* d_in, const int* in_sizes, int n_in,
                              void* d_out, int out_size) {
  const float* x  = (const float*)d_in[0];
  const float* ms = (const float*)d_in[1];
  if (n_in >= 2 && in_sizes[0] == 2306) {
    x  = (const float*)d_in[1];
    ms = (const float*)d_in[0];
  }
  float* out = (float*)d_out;

  setup_w0_kernel<<<(K_LENM * K_M + 255) / 256, 256>>>(ms);
  setup_w1_tail_kernel<<<32, 256>>>(ms, out, out_size);

  cudaFuncSetAttribute(pred_kernel,
                       cudaFuncAttributeMaxDynamicSharedMemorySize, SM_TOTAL);
  dim3 grid(K_N / 128, 4);
  pred_kernel<<<grid, 256, SM_TOTAL>>>(x, out);
}

// round 11
// speedup vs baseline: 2.7098x; 1.0513x over previous
#include <cuda_runtime.h>
#include <cuda_bf16.h>
#include <cstdint>
#include <math.h>

// =====================================================================
// NN_Model_19748259627524 — Bayesian NN sampling forward pass.
// R11: BOTH stages on tensor cores (mma.sync bf16, HMMA) with exact-
// compensated 3-term hi/lo splits:
//   stage-1: z = relu(x@W0_m):  xh*wh + xl*wh + xh*wl   (K=32/term, d=17)
//   stage-2: pred = z@W1 + b:   zh*Wh + zl*Wh + zh*Wl   (K=64/term, h=64)
// Software-pipelined m-loop (2 barriers/iter), W0-split double buffer.
// Setup kernels merged (2 launches/replay -> ncu -s5 hits pred_kernel).
// =====================================================================

#define JAX_PARTITIONABLE 1

#define K_N     16384
#define K_D     17
#define K_H     64
#define K_M     100
#define K_LENM  1088
#define K_MPRI  65
#define PRED_ELEMS 163840000LL   // 16384*100*100

__device__ float g_w0[K_M * K_LENM];   // [m][i], i = d*64+h
__device__ float g_w1[K_MPRI * K_M];   // [d][c]

// ---------------------------------------------------------------------
// threefry2x32 (JAX rotation schedule)
// ---------------------------------------------------------------------
__device__ __forceinline__ void tf2x32(unsigned k0, unsigned k1,
                                       unsigned x0, unsigned x1,
                                       unsigned &o0, unsigned &o1) {
  unsigned ks2 = k0 ^ k1 ^ 0x1BD11BDAu;
  x0 += k0; x1 += k1;
#define TF_R(r) { x0 += x1; x1 = (x1 << (r)) | (x1 >> (32 - (r))); x1 ^= x0; }
  TF_R(13) TF_R(15) TF_R(26) TF_R(6)  x0 += k1;  x1 += ks2 + 1u;
  TF_R(17) TF_R(29) TF_R(16) TF_R(24) x0 += ks2; x1 += k0 + 2u;
  TF_R(13) TF_R(15) TF_R(26) TF_R(6)  x0 += k0;  x1 += k1 + 3u;
  TF_R(17) TF_R(29) TF_R(16) TF_R(24) x0 += k1;  x1 += ks2 + 4u;
  TF_R(13) TF_R(15) TF_R(26) TF_R(6)  x0 += ks2; x1 += k0 + 5u;
#undef TF_R
  o0 = x0; o1 = x1;
}

__device__ __forceinline__ void get_key(unsigned which, unsigned &s0, unsigned &s1) {
#if JAX_PARTITIONABLE
  tf2x32(0u, 42u, 0u, which, s0, s1);
#else
  unsigned a0, a1, b0, b1;
  tf2x32(0u, 42u, 0u, 2u, a0, a1);
  tf2x32(0u, 42u, 1u, 3u, b0, b1);
  if (which == 0u) { s0 = a0; s1 = b0; } else { s0 = a1; s1 = b1; }
#endif
}

__device__ __forceinline__ float jax_normal(unsigned k0, unsigned k1,
                                            unsigned idx, unsigned half) {
  unsigned a, b, bits;
#if JAX_PARTITIONABLE
  tf2x32(k0, k1, 0u, idx, a, b);
  bits = a ^ b;
#else
  if (idx < half) { tf2x32(k0, k1, idx, idx + half, a, b); bits = a; }
  else            { tf2x32(k0, k1, idx - half, idx, a, b); bits = b; }
#endif
  float u = __uint_as_float((bits >> 9) | 0x3f800000u) - 1.0f;
  float v = fmaf(u, 1.99999994f, -0.99999994f);
  v = fmaxf(v, -0.99999994f);
  return 1.41421356237f * erfinvf(v);
}

// ---------------------------------------------------------------------
// merged setup kernel (grid 425 x 256 covers all pieces)
// ---------------------------------------------------------------------
__global__ void setup_kernel(const float* __restrict__ ms,
                             float* __restrict__ out, int out_size) {
  int j = blockIdx.x * blockDim.x + threadIdx.x;
  if (j < K_LENM * K_M) {
    unsigned s0, s1; get_key(0u, s0, s1);
    float eps = jax_normal(s0, s1, (unsigned)j, 54400u);
    int i = j / K_M;
    int m = j - i * K_M;
    float vv = fabsf(ms[1153 + i]) + 1e-6f;
    g_w0[m * K_LENM + i] = fmaf(eps, sqrtf(vv), ms[i]);
  }
  if (j < K_MPRI * K_M) {
    unsigned s0, s1; get_key(1u, s0, s1);
    float eps = jax_normal(s0, s1, (unsigned)j, 3250u);
    int d = j / K_M;
    float vv = fabsf(ms[2241 + d]) + 1e-6f;
    g_w1[j] = fmaf(eps, sqrtf(vv), ms[1088 + d]);
  }
  if ((long long)out_size >= PRED_ELEMS + 2306LL) {
    size_t P = (size_t)PRED_ELEMS;
    if (j < 1088) {
      out[P + j]        = ms[j];
      out[P + 1088 + j] = fabsf(ms[1153 + j]) + 1e-6f;
    }
    if (j < 65) {
      out[P + 2176 + j] = ms[1088 + j];
      out[P + 2241 + j] = fabsf(ms[2241 + j]) + 1e-6f;
    }
  }
}

// ---------------------------------------------------------------------
// warp-MMA helpers
// ---------------------------------------------------------------------
__device__ __forceinline__ uint32_t smem_u32(const void* p) {
  uint32_t a;
  asm("{ .reg .u64 t; cvta.to.shared.u64 t, %1; cvt.u32.u64 %0, t; }"
      : "=r"(a) : "l"(p));
  return a;
}

__device__ __forceinline__ void ldsm_x4(uint32_t &r0, uint32_t &r1,
                                        uint32_t &r2, uint32_t &r3,
                                        uint32_t addr) {
  asm volatile("ldmatrix.sync.aligned.m8n8.x4.shared.b16 {%0,%1,%2,%3}, [%4];"
               : "=r"(r0), "=r"(r1), "=r"(r2), "=r"(r3) : "r"(addr));
}

__device__ __forceinline__ void mma_bf16(float &c0, float &c1, float &c2, float &c3,
                                         uint32_t a0, uint32_t a1, uint32_t a2, uint32_t a3,
                                         uint32_t b0, uint32_t b1) {
  asm volatile(
      "mma.sync.aligned.m16n8k16.row.col.f32.bf16.bf16.f32 "
      "{%0,%1,%2,%3}, {%4,%5,%6,%7}, {%8,%9}, {%0,%1,%2,%3};"
      : "+f"(c0), "+f"(c1), "+f"(c2), "+f"(c3)
      : "r"(a0), "r"(a1), "r"(a2), "r"(a3), "r"(b0), "r"(b1));
}

// ---------------------------------------------------------------------
// smem layout (bytes)
// ---------------------------------------------------------------------
#define ASTRIDE 272        // A'/B' row stride (128 k bf16 + pad)
#define XSTRIDE 144        // xsplit/w0split row stride (64 k bf16 + pad)
#define SM_A    0          // 128*272 = 34816   A' = [zh|zl] per n
#define SM_B    34816      // 112*272 = 30464   B' = [W1h|W1l] per c
#define SM_XS   65280      // 128*144 = 18432   xsplit = [xh|xl] per n
#define SM_W0S  83712      // 2 x 64*144 = 18432 (double buffer) [wh|wl] per h
#define SM_BIAS 102144     // 128*4 = 512
#define SM_TOTAL 102656

#define W0SBUF  9216       // 64*144

__constant__ int g_akp[6] = {0, 1, 2, 3, 0, 1};  // stage-2 A k-pair idx
__constant__ int g_bkp[6] = {0, 1, 0, 1, 2, 3};  // stage-2 B k-pair idx

// stage-1 MMA: 3 groups, (A k-pair, B k-pair): (0,0),(1,0),(0,1)
__device__ __forceinline__ void stage1_group(int g1, uint32_t a1_base,
                                             uint32_t b1_base,
                                             float (&zacc)[8][4]) {
  const int ap = (g1 == 1) ? 1 : 0;
  const int bp = (g1 == 2) ? 1 : 0;
  uint32_t a1f[2][4];
#pragma unroll
  for (int s2 = 0; s2 < 2; ++s2)
    ldsm_x4(a1f[s2][0], a1f[s2][1], a1f[s2][2], a1f[s2][3],
            a1_base + (uint32_t)((ap * 2 + s2) * 32));
#pragma unroll
  for (int j = 0; j < 8; ++j) {
    uint32_t bf[4];
    ldsm_x4(bf[0], bf[1], bf[2], bf[3],
            b1_base + (uint32_t)(j * 8 * XSTRIDE + bp * 64));
    mma_bf16(zacc[j][0], zacc[j][1], zacc[j][2], zacc[j][3],
             a1f[0][0], a1f[0][1], a1f[0][2], a1f[0][3], bf[0], bf[1]);
    mma_bf16(zacc[j][0], zacc[j][1], zacc[j][2], zacc[j][3],
             a1f[1][0], a1f[1][1], a1f[1][2], a1f[1][3], bf[2], bf[3]);
  }
}

__global__ void __launch_bounds__(256, 2)
pred_kernel(const float* __restrict__ x, float* __restrict__ out) {
  extern __shared__ char smem[];
  const uint32_t sbase = smem_u32(smem);
  float* bias_s = (float*)(smem + SM_BIAS);

  const int tid  = threadIdx.x;
  const int wid  = tid >> 5;
  const int lane = tid & 31;
  const int n0 = blockIdx.x * 128;
  const int mbase = blockIdx.y * 25;

  // ---- zero xsplit + both w0split buffers (36864 B contiguous) ----
  {
    int4* z = (int4*)(smem + SM_XS);
#pragma unroll
    for (int k = 0; k < 9; ++k) z[tid + k * 256] = make_int4(0, 0, 0, 0);
  }
  __syncthreads();

  // ---- build B' = [W1h | W1l] rows c (zero-pad c>=100), and bias ----
  for (int idx = tid; idx < 112 * 32; idx += 256) {
    int c = idx >> 5;
    int h0 = (idx & 31) * 2;
    float v0 = (c < K_M) ? g_w1[(h0 + 1) * K_M + c] : 0.0f;
    float v1 = (c < K_M) ? g_w1[(h0 + 2) * K_M + c] : 0.0f;
    __nv_bfloat162 h2, l2;
    h2.x = __float2bfloat16(v0);
    h2.y = __float2bfloat16(v1);
    l2.x = __float2bfloat16(v0 - __bfloat162float(h2.x));
    l2.y = __float2bfloat16(v1 - __bfloat162float(h2.y));
    char* row = smem + SM_B + c * ASTRIDE;
    *(__nv_bfloat162*)(row + h0 * 2)       = h2;
    *(__nv_bfloat162*)(row + 128 + h0 * 2) = l2;
  }
  if (tid < 128) bias_s[tid] = (tid < K_M) ? g_w1[tid] : 0.0f;

  // ---- build xsplit: [n][k] k: xh at d, xl at 32+d ----
  for (int idx = tid; idx < 128 * K_D; idx += 256) {
    int n = idx / K_D, d = idx - n * K_D;
    float v = x[(size_t)n0 * K_D + idx];
    __nv_bfloat16 h = __float2bfloat16(v);
    __nv_bfloat16 l = __float2bfloat16(v - __bfloat162float(h));
    char* row = smem + SM_XS + n * XSTRIDE;
    *(__nv_bfloat16*)(row + d * 2)      = h;
    *(__nv_bfloat16*)(row + 64 + d * 2) = l;
  }

  // ---- build w0split(m0) into buf0 ----
  {
    const float* src = g_w0 + (size_t)mbase * K_LENM;
#pragma unroll
    for (int k = 0; k < 5; ++k) {
      int idx = tid + k * 256;
      if (idx < K_LENM) {
        float v = src[idx];
        int d = idx >> 6, h = idx & 63;
        __nv_bfloat16 hi = __float2bfloat16(v);
        __nv_bfloat16 lo = __float2bfloat16(v - __bfloat162float(hi));
        char* row = smem + SM_W0S + h * XSTRIDE;
        *(__nv_bfloat16*)(row + d * 2)      = hi;
        *(__nv_bfloat16*)(row + 64 + d * 2) = lo;
      }
    }
  }
  __syncthreads();

  // lane bases
  const uint32_t a1_base = sbase + SM_XS +
      (uint32_t)((wid * 16 + (lane & 15)) * XSTRIDE + ((lane >> 4) * 8) * 2);
  const uint32_t b1_off = (uint32_t)((lane & 7) * XSTRIDE + ((lane >> 3) * 8) * 2);

  const int wr = wid >> 1;           // stage-2 row warp
  const int wc = wid & 1;            // stage-2 col warp
  const int cbase = wc * 56;
  const int nct = wc ? 6 : 7;
  const int trow = lane >> 2;
  const int tcol = (lane & 3) * 2;

  const uint32_t a_base = sbase + SM_A +
      (uint32_t)((wr * 32 + (lane & 15)) * ASTRIDE + ((lane >> 4) * 8) * 2);
  const uint32_t b_base = sbase + SM_B +
      (uint32_t)((cbase + (lane & 7)) * ASTRIDE + ((lane >> 3) * 8) * 2);

  // ---- stage-1 prologue MMA for mi=0 ----
  float zacc[8][4];
#pragma unroll
  for (int j = 0; j < 8; ++j)
#pragma unroll
    for (int q = 0; q < 4; ++q) zacc[j][q] = 0.0f;
  {
    uint32_t b1_base = sbase + SM_W0S + b1_off;
#pragma unroll
    for (int g1 = 0; g1 < 3; ++g1)
      stage1_group(g1, a1_base, b1_base, zacc);
  }

  // prefetch w0(m1)
  float pf[5];
  {
    const float* src = g_w0 + (size_t)(mbase + 1) * K_LENM;
#pragma unroll
    for (int k = 0; k < 5; ++k) {
      int idx = tid + k * 256;
      pf[k] = src[idx < K_LENM ? idx : 0];
    }
  }

  for (int mi = 0; mi < 25; ++mi) {
    const int m = mbase + mi;

    // ======== phase A: publish A'(zacc), publish w0split(m+1) ========
#pragma unroll
    for (int j = 0; j < 8; ++j) {
      int h0 = j * 8 + tcol;
      int r0 = wid * 16 + trow;
      {
        float z0 = fmaxf(zacc[j][0], 0.0f);
        float z1 = fmaxf(zacc[j][1], 0.0f);
        __nv_bfloat162 h2, l2;
        h2.x = __float2bfloat16(z0);
        h2.y = __float2bfloat16(z1);
        l2.x = __float2bfloat16(z0 - __bfloat162float(h2.x));
        l2.y = __float2bfloat16(z1 - __bfloat162float(h2.y));
        char* row = smem + SM_A + r0 * ASTRIDE;
        *(__nv_bfloat162*)(row + h0 * 2)       = h2;
        *(__nv_bfloat162*)(row + 128 + h0 * 2) = l2;
      }
      {
        float z0 = fmaxf(zacc[j][2], 0.0f);
        float z1 = fmaxf(zacc[j][3], 0.0f);
        __nv_bfloat162 h2, l2;
        h2.x = __float2bfloat16(z0);
        h2.y = __float2bfloat16(z1);
        l2.x = __float2bfloat16(z0 - __bfloat162float(h2.x));
        l2.y = __float2bfloat16(z1 - __bfloat162float(h2.y));
        char* row = smem + SM_A + (r0 + 8) * ASTRIDE;
        *(__nv_bfloat162*)(row + h0 * 2)       = h2;
        *(__nv_bfloat162*)(row + 128 + h0 * 2) = l2;
      }
    }
    if (mi + 1 < 25) {
      char* buf = smem + SM_W0S + ((mi + 1) & 1) * W0SBUF;
#pragma unroll
      for (int k = 0; k < 5; ++k) {
        int idx = tid + k * 256;
        if (idx < K_LENM) {
          float v = pf[k];
          int d = idx >> 6, h = idx & 63;
          __nv_bfloat16 hi = __float2bfloat16(v);
          __nv_bfloat16 lo = __float2bfloat16(v - __bfloat162float(hi));
          char* row = buf + h * XSTRIDE;
          *(__nv_bfloat16*)(row + d * 2)      = hi;
          *(__nv_bfloat16*)(row + 64 + d * 2) = lo;
        }
      }
    }
    __syncthreads();

    // ======== phase B ========
    const int do_next = (mi + 1 < 25);
    const uint32_t b1_base =
        sbase + SM_W0S + (uint32_t)(((mi + 1) & 1) * W0SBUF) + b1_off;

    // prefetch w0(m+2)
    if (mi + 2 < 25) {
      const float* src = g_w0 + (size_t)(m + 2) * K_LENM;
#pragma unroll
      for (int k = 0; k < 5; ++k) {
        int idx = tid + k * 256;
        pf[k] = src[idx < K_LENM ? idx : 0];
      }
    }

    // zero zacc for m+1
#pragma unroll
    for (int j = 0; j < 8; ++j)
#pragma unroll
      for (int q = 0; q < 4; ++q) zacc[j][q] = 0.0f;

#pragma unroll
    for (int pass = 0; pass < 2; ++pass) {
      const int jbase = pass ? 4 : 0;
      const int jcnt  = pass ? (nct - 4) : 4;
      float acc[2][4][4];
#pragma unroll
      for (int i = 0; i < 2; ++i)
#pragma unroll
        for (int j = 0; j < 4; ++j)
#pragma unroll
          for (int q = 0; q < 4; ++q) acc[i][j][q] = 0.0f;

#pragma unroll
      for (int g = 0; g < 6; ++g) {
        // interleave stage-1(m+1) groups at slots 1, 5, 9
        const int s = pass * 6 + g;
        if (do_next && (s == 1 || s == 5 || s == 9)) {
          const int g1 = (s == 1) ? 0 : ((s == 5) ? 1 : 2);
          stage1_group(g1, a1_base, b1_base, zacc);
        }
        // stage-2 MMA group g
        const int akp = g_akp[g];
        const int bkp = g_bkp[g];
        uint32_t af[2][2][4];
#pragma unroll
        for (int i = 0; i < 2; ++i)
#pragma unroll
          for (int s2 = 0; s2 < 2; ++s2) {
            uint32_t addr = a_base + (uint32_t)(i * 16) * ASTRIDE +
                            (uint32_t)((akp * 2 + s2) * 16) * 2;
            ldsm_x4(af[i][s2][0], af[i][s2][1], af[i][s2][2], af[i][s2][3], addr);
          }
#pragma unroll
        for (int j = 0; j < 4; ++j) {
          if (j >= jcnt) break;
          uint32_t bf[4];
          uint32_t addr = b_base + (uint32_t)((jbase + j) * 8) * ASTRIDE +
                          (uint32_t)(bkp * 32) * 2;
          ldsm_x4(bf[0], bf[1], bf[2], bf[3], addr);
#pragma unroll
          for (int i = 0; i < 2; ++i) {
            mma_bf16(acc[i][j][0], acc[i][j][1], acc[i][j][2], acc[i][j][3],
                     af[i][0][0], af[i][0][1], af[i][0][2], af[i][0][3],
                     bf[0], bf[1]);
            mma_bf16(acc[i][j][0], acc[i][j][1], acc[i][j][2], acc[i][j][3],
                     af[i][1][0], af[i][1][1], af[i][1][2], af[i][1][3],
                     bf[2], bf[3]);
          }
        }
      }

      // ---- store this pass (c<100 only), bias added here ----
#pragma unroll
      for (int i = 0; i < 2; ++i) {
        int nrow = n0 + wr * 32 + i * 16 + trow;
        float* p0 = out + (size_t)nrow * 10000u + (unsigned)m * 100u;
#pragma unroll
        for (int j = 0; j < 4; ++j) {
          if (j >= jcnt) break;
          int c = cbase + (jbase + j) * 8 + tcol;
          if (c < K_M) {
            float b0 = bias_s[c], b1 = bias_s[c + 1];
            *(float2*)(p0 + c) =
                make_float2(acc[i][j][0] + b0, acc[i][j][1] + b1);
            *(float2*)(p0 + 8 * 10000u + c) =
                make_float2(acc[i][j][2] + b0, acc[i][j][3] + b1);
          }
        }
      }
    }
    __syncthreads();   // A' & w0split buffers free for next phase A
  }
}

// ---------------------------------------------------------------------
extern "C" void kernel_launch(void* const* d_in, const int* in_sizes, int n_in,
                              void* d_out, int out_size) {
  const float* x  = (const float*)d_in[0];
  const float* ms = (const float*)d_in[1];
  if (n_in >= 2 && in_sizes[0] == 2306) {
    x  = (const float*)d_in[1];
    ms = (const float*)d_in[0];
  }
  float* out = (float*)d_out;

  setup_kernel<<<(K_LENM * K_M + 255) / 256, 256>>>(ms, out, out_size);

  cudaFuncSetAttribute(pred_kernel,
                       cudaFuncAttributeMaxDynamicSharedMemorySize, SM_TOTAL);
  dim3 grid(K_N / 128, 4);
  pred_kernel<<<grid, 256, SM_TOTAL>>>(x, out);
}

// round 12
// speedup vs baseline: 2.8900x; 1.0665x over previous
#include <cuda_runtime.h>
#include <cuda_bf16.h>
#include <cstdint>
#include <math.h>

// =====================================================================
// NN_Model_19748259627524 — Bayesian NN sampling forward pass.
// Both stages on HMMA (mma.sync bf16) with exact-compensated 3-term
// hi/lo splits. R12: fragment-reuse restructure to cut L1TEX traffic:
//   stage-2: bp-sections {0,2},{1,3} reuse A-pair frags (48->32 x4)
//            and hold B tile frags per section (42->28 x4)
//   stage-1: x frags loaded once per m, B once per (tile,bp) (30->20 x4)
// =====================================================================

#define JAX_PARTITIONABLE 1

#define K_N     16384
#define K_D     17
#define K_H     64
#define K_M     100
#define K_LENM  1088
#define K_MPRI  65
#define PRED_ELEMS 163840000LL   // 16384*100*100

__device__ float g_w0[K_M * K_LENM];   // [m][i], i = d*64+h
__device__ float g_w1[K_MPRI * K_M];   // [d][c]

// ---------------------------------------------------------------------
// threefry2x32 (JAX rotation schedule)
// ---------------------------------------------------------------------
__device__ __forceinline__ void tf2x32(unsigned k0, unsigned k1,
                                       unsigned x0, unsigned x1,
                                       unsigned &o0, unsigned &o1) {
  unsigned ks2 = k0 ^ k1 ^ 0x1BD11BDAu;
  x0 += k0; x1 += k1;
#define TF_R(r) { x0 += x1; x1 = (x1 << (r)) | (x1 >> (32 - (r))); x1 ^= x0; }
  TF_R(13) TF_R(15) TF_R(26) TF_R(6)  x0 += k1;  x1 += ks2 + 1u;
  TF_R(17) TF_R(29) TF_R(16) TF_R(24) x0 += ks2; x1 += k0 + 2u;
  TF_R(13) TF_R(15) TF_R(26) TF_R(6)  x0 += k0;  x1 += k1 + 3u;
  TF_R(17) TF_R(29) TF_R(16) TF_R(24) x0 += k1;  x1 += ks2 + 4u;
  TF_R(13) TF_R(15) TF_R(26) TF_R(6)  x0 += ks2; x1 += k0 + 5u;
#undef TF_R
  o0 = x0; o1 = x1;
}

__device__ __forceinline__ void get_key(unsigned which, unsigned &s0, unsigned &s1) {
#if JAX_PARTITIONABLE
  tf2x32(0u, 42u, 0u, which, s0, s1);
#else
  unsigned a0, a1, b0, b1;
  tf2x32(0u, 42u, 0u, 2u, a0, a1);
  tf2x32(0u, 42u, 1u, 3u, b0, b1);
  if (which == 0u) { s0 = a0; s1 = b0; } else { s0 = a1; s1 = b1; }
#endif
}

__device__ __forceinline__ float jax_normal(unsigned k0, unsigned k1,
                                            unsigned idx, unsigned half) {
  unsigned a, b, bits;
#if JAX_PARTITIONABLE
  tf2x32(k0, k1, 0u, idx, a, b);
  bits = a ^ b;
#else
  if (idx < half) { tf2x32(k0, k1, idx, idx + half, a, b); bits = a; }
  else            { tf2x32(k0, k1, idx - half, idx, a, b); bits = b; }
#endif
  float u = __uint_as_float((bits >> 9) | 0x3f800000u) - 1.0f;
  float v = fmaf(u, 1.99999994f, -0.99999994f);
  v = fmaxf(v, -0.99999994f);
  return 1.41421356237f * erfinvf(v);
}

// ---------------------------------------------------------------------
// merged setup kernel
// ---------------------------------------------------------------------
__global__ void setup_kernel(const float* __restrict__ ms,
                             float* __restrict__ out, int out_size) {
  int j = blockIdx.x * blockDim.x + threadIdx.x;
  if (j < K_LENM * K_M) {
    unsigned s0, s1; get_key(0u, s0, s1);
    float eps = jax_normal(s0, s1, (unsigned)j, 54400u);
    int i = j / K_M;
    int m = j - i * K_M;
    float vv = fabsf(ms[1153 + i]) + 1e-6f;
    g_w0[m * K_LENM + i] = fmaf(eps, sqrtf(vv), ms[i]);
  }
  if (j < K_MPRI * K_M) {
    unsigned s0, s1; get_key(1u, s0, s1);
    float eps = jax_normal(s0, s1, (unsigned)j, 3250u);
    int d = j / K_M;
    float vv = fabsf(ms[2241 + d]) + 1e-6f;
    g_w1[j] = fmaf(eps, sqrtf(vv), ms[1088 + d]);
  }
  if ((long long)out_size >= PRED_ELEMS + 2306LL) {
    size_t P = (size_t)PRED_ELEMS;
    if (j < 1088) {
      out[P + j]        = ms[j];
      out[P + 1088 + j] = fabsf(ms[1153 + j]) + 1e-6f;
    }
    if (j < 65) {
      out[P + 2176 + j] = ms[1088 + j];
      out[P + 2241 + j] = fabsf(ms[2241 + j]) + 1e-6f;
    }
  }
}

// ---------------------------------------------------------------------
// warp-MMA helpers
// ---------------------------------------------------------------------
__device__ __forceinline__ uint32_t smem_u32(const void* p) {
  uint32_t a;
  asm("{ .reg .u64 t; cvta.to.shared.u64 t, %1; cvt.u32.u64 %0, t; }"
      : "=r"(a) : "l"(p));
  return a;
}

__device__ __forceinline__ void ldsm_x4(uint32_t &r0, uint32_t &r1,
                                        uint32_t &r2, uint32_t &r3,
                                        uint32_t addr) {
  asm volatile("ldmatrix.sync.aligned.m8n8.x4.shared.b16 {%0,%1,%2,%3}, [%4];"
               : "=r"(r0), "=r"(r1), "=r"(r2), "=r"(r3) : "r"(addr));
}

__device__ __forceinline__ void mma_bf16(float &c0, float &c1, float &c2, float &c3,
                                         uint32_t a0, uint32_t a1, uint32_t a2, uint32_t a3,
                                         uint32_t b0, uint32_t b1) {
  asm volatile(
      "mma.sync.aligned.m16n8k16.row.col.f32.bf16.bf16.f32 "
      "{%0,%1,%2,%3}, {%4,%5,%6,%7}, {%8,%9}, {%0,%1,%2,%3};"
      : "+f"(c0), "+f"(c1), "+f"(c2), "+f"(c3)
      : "r"(a0), "r"(a1), "r"(a2), "r"(a3), "r"(b0), "r"(b1));
}

// ---------------------------------------------------------------------
// smem layout (bytes)
// ---------------------------------------------------------------------
#define ASTRIDE 272        // A'/B' row stride (128 k bf16 + pad)
#define XSTRIDE 144        // xsplit/w0split row stride (64 k bf16 + pad)
#define SM_A    0          // 128*272 = 34816   A' = [zh|zl] per n
#define SM_B    34816      // 112*272 = 30464   B' = [W1h|W1l] per c
#define SM_XS   65280      // 128*144 = 18432   xsplit = [xh|xl] per n
#define SM_W0S  83712      // 2 x 64*144 = 18432 (double buffer) [wh|wl] per h
#define SM_BIAS 102144     // 128*4 = 512
#define SM_TOTAL 102656

#define W0SBUF  9216       // 64*144

// ---------------------------------------------------------------------
// stage-1: zacc += [xh|xl] @ [wh|wl] 3-term  (x frags loaded here, 20 x4)
// ---------------------------------------------------------------------
__device__ __forceinline__ void stage1_mma(uint32_t a1_base, uint32_t b1_base,
                                           float (&zacc)[8][4]) {
  uint32_t xa[2][2][4];   // [ap][kstep][regs]
#pragma unroll
  for (int ap = 0; ap < 2; ++ap)
#pragma unroll
    for (int s = 0; s < 2; ++s)
      ldsm_x4(xa[ap][s][0], xa[ap][s][1], xa[ap][s][2], xa[ap][s][3],
              a1_base + (uint32_t)((ap * 2 + s) * 32));

  // term bp=0 (wh): ap0 (xh) + ap1 (xl)
#pragma unroll
  for (int j = 0; j < 8; ++j) {
    uint32_t bf[4];
    ldsm_x4(bf[0], bf[1], bf[2], bf[3],
            b1_base + (uint32_t)(j * 8 * XSTRIDE));
    mma_bf16(zacc[j][0], zacc[j][1], zacc[j][2], zacc[j][3],
             xa[0][0][0], xa[0][0][1], xa[0][0][2], xa[0][0][3], bf[0], bf[1]);
    mma_bf16(zacc[j][0], zacc[j][1], zacc[j][2], zacc[j][3],
             xa[0][1][0], xa[0][1][1], xa[0][1][2], xa[0][1][3], bf[2], bf[3]);
    mma_bf16(zacc[j][0], zacc[j][1], zacc[j][2], zacc[j][3],
             xa[1][0][0], xa[1][0][1], xa[1][0][2], xa[1][0][3], bf[0], bf[1]);
    mma_bf16(zacc[j][0], zacc[j][1], zacc[j][2], zacc[j][3],
             xa[1][1][0], xa[1][1][1], xa[1][1][2], xa[1][1][3], bf[2], bf[3]);
  }
  // term bp=1 (wl): ap0 (xh)
#pragma unroll
  for (int j = 0; j < 8; ++j) {
    uint32_t bf[4];
    ldsm_x4(bf[0], bf[1], bf[2], bf[3],
            b1_base + (uint32_t)(j * 8 * XSTRIDE + 64));
    mma_bf16(zacc[j][0], zacc[j][1], zacc[j][2], zacc[j][3],
             xa[0][0][0], xa[0][0][1], xa[0][0][2], xa[0][0][3], bf[0], bf[1]);
    mma_bf16(zacc[j][0], zacc[j][1], zacc[j][2], zacc[j][3],
             xa[0][1][0], xa[0][1][1], xa[0][1][2], xa[0][1][3], bf[2], bf[3]);
  }
}

__global__ void __launch_bounds__(256, 2)
pred_kernel(const float* __restrict__ x, float* __restrict__ out) {
  extern __shared__ char smem[];
  const uint32_t sbase = smem_u32(smem);
  float* bias_s = (float*)(smem + SM_BIAS);

  const int tid  = threadIdx.x;
  const int wid  = tid >> 5;
  const int lane = tid & 31;
  const int n0 = blockIdx.x * 128;
  const int mbase = blockIdx.y * 25;

  // ---- zero xsplit + both w0split buffers ----
  {
    int4* z = (int4*)(smem + SM_XS);
#pragma unroll
    for (int k = 0; k < 9; ++k) z[tid + k * 256] = make_int4(0, 0, 0, 0);
  }
  __syncthreads();

  // ---- build B' = [W1h | W1l] rows c, and bias ----
  for (int idx = tid; idx < 112 * 32; idx += 256) {
    int c = idx >> 5;
    int h0 = (idx & 31) * 2;
    float v0 = (c < K_M) ? g_w1[(h0 + 1) * K_M + c] : 0.0f;
    float v1 = (c < K_M) ? g_w1[(h0 + 2) * K_M + c] : 0.0f;
    __nv_bfloat162 h2, l2;
    h2.x = __float2bfloat16(v0);
    h2.y = __float2bfloat16(v1);
    l2.x = __float2bfloat16(v0 - __bfloat162float(h2.x));
    l2.y = __float2bfloat16(v1 - __bfloat162float(h2.y));
    char* row = smem + SM_B + c * ASTRIDE;
    *(__nv_bfloat162*)(row + h0 * 2)       = h2;
    *(__nv_bfloat162*)(row + 128 + h0 * 2) = l2;
  }
  if (tid < 128) bias_s[tid] = (tid < K_M) ? g_w1[tid] : 0.0f;

  // ---- build xsplit: [n][k]  xh at d*2, xl at 64+d*2 ----
  for (int idx = tid; idx < 128 * K_D; idx += 256) {
    int n = idx / K_D, d = idx - n * K_D;
    float v = x[(size_t)n0 * K_D + idx];
    __nv_bfloat16 h = __float2bfloat16(v);
    __nv_bfloat16 l = __float2bfloat16(v - __bfloat162float(h));
    char* row = smem + SM_XS + n * XSTRIDE;
    *(__nv_bfloat16*)(row + d * 2)      = h;
    *(__nv_bfloat16*)(row + 64 + d * 2) = l;
  }

  // ---- build w0split(m0) into buf0 ----
  {
    const float* src = g_w0 + (size_t)mbase * K_LENM;
#pragma unroll
    for (int k = 0; k < 5; ++k) {
      int idx = tid + k * 256;
      if (idx < K_LENM) {
        float v = src[idx];
        int d = idx >> 6, h = idx & 63;
        __nv_bfloat16 hi = __float2bfloat16(v);
        __nv_bfloat16 lo = __float2bfloat16(v - __bfloat162float(hi));
        char* row = smem + SM_W0S + h * XSTRIDE;
        *(__nv_bfloat16*)(row + d * 2)      = hi;
        *(__nv_bfloat16*)(row + 64 + d * 2) = lo;
      }
    }
  }
  __syncthreads();

  // lane bases
  const uint32_t a1_base = sbase + SM_XS +
      (uint32_t)((wid * 16 + (lane & 15)) * XSTRIDE + ((lane >> 4) * 8) * 2);
  const uint32_t b1_off = (uint32_t)((lane & 7) * XSTRIDE + ((lane >> 3) * 8) * 2);

  const int wr = wid >> 1;           // stage-2 row warp
  const int wc = wid & 1;            // stage-2 col warp
  const int cbase = wc * 56;
  const int nct = wc ? 6 : 7;
  const int trow = lane >> 2;
  const int tcol = (lane & 3) * 2;

  const uint32_t a_base = sbase + SM_A +
      (uint32_t)((wr * 32 + (lane & 15)) * ASTRIDE + ((lane >> 4) * 8) * 2);
  const uint32_t b_base = sbase + SM_B +
      (uint32_t)((cbase + (lane & 7)) * ASTRIDE + ((lane >> 3) * 8) * 2);

  // ---- stage-1 prologue for mi=0 ----
  float zacc[8][4];
#pragma unroll
  for (int j = 0; j < 8; ++j)
#pragma unroll
    for (int q = 0; q < 4; ++q) zacc[j][q] = 0.0f;
  stage1_mma(a1_base, sbase + SM_W0S + b1_off, zacc);

  // prefetch w0(m1)
  float pf[5];
  {
    const float* src = g_w0 + (size_t)(mbase + 1) * K_LENM;
#pragma unroll
    for (int k = 0; k < 5; ++k) {
      int idx = tid + k * 256;
      pf[k] = src[idx < K_LENM ? idx : 0];
    }
  }

  for (int mi = 0; mi < 25; ++mi) {
    const int m = mbase + mi;

    // ======== phase A: publish A'(zacc), publish w0split(m+1) ========
#pragma unroll
    for (int j = 0; j < 8; ++j) {
      int h0 = j * 8 + tcol;
      int r0 = wid * 16 + trow;
      {
        float z0 = fmaxf(zacc[j][0], 0.0f);
        float z1 = fmaxf(zacc[j][1], 0.0f);
        __nv_bfloat162 h2, l2;
        h2.x = __float2bfloat16(z0);
        h2.y = __float2bfloat16(z1);
        l2.x = __float2bfloat16(z0 - __bfloat162float(h2.x));
        l2.y = __float2bfloat16(z1 - __bfloat162float(h2.y));
        char* row = smem + SM_A + r0 * ASTRIDE;
        *(__nv_bfloat162*)(row + h0 * 2)       = h2;
        *(__nv_bfloat162*)(row + 128 + h0 * 2) = l2;
      }
      {
        float z0 = fmaxf(zacc[j][2], 0.0f);
        float z1 = fmaxf(zacc[j][3], 0.0f);
        __nv_bfloat162 h2, l2;
        h2.x = __float2bfloat16(z0);
        h2.y = __float2bfloat16(z1);
        l2.x = __float2bfloat16(z0 - __bfloat162float(h2.x));
        l2.y = __float2bfloat16(z1 - __bfloat162float(h2.y));
        char* row = smem + SM_A + (r0 + 8) * ASTRIDE;
        *(__nv_bfloat162*)(row + h0 * 2)       = h2;
        *(__nv_bfloat162*)(row + 128 + h0 * 2) = l2;
      }
    }
    if (mi + 1 < 25) {
      char* buf = smem + SM_W0S + ((mi + 1) & 1) * W0SBUF;
#pragma unroll
      for (int k = 0; k < 5; ++k) {
        int idx = tid + k * 256;
        if (idx < K_LENM) {
          float v = pf[k];
          int d = idx >> 6, h = idx & 63;
          __nv_bfloat16 hi = __float2bfloat16(v);
          __nv_bfloat16 lo = __float2bfloat16(v - __bfloat162float(hi));
          char* row = buf + h * XSTRIDE;
          *(__nv_bfloat16*)(row + d * 2)      = hi;
          *(__nv_bfloat16*)(row + 64 + d * 2) = lo;
        }
      }
    }
    __syncthreads();

    // ======== phase B ========
    const int do_next = (mi + 1 < 25);
    const uint32_t b1_base =
        sbase + SM_W0S + (uint32_t)(((mi + 1) & 1) * W0SBUF) + b1_off;

    // prefetch w0(m+2)
    if (mi + 2 < 25) {
      const float* src = g_w0 + (size_t)(m + 2) * K_LENM;
#pragma unroll
      for (int k = 0; k < 5; ++k) {
        int idx = tid + k * 256;
        pf[k] = src[idx < K_LENM ? idx : 0];
      }
    }

#pragma unroll
    for (int pass = 0; pass < 2; ++pass) {
      const int jbase = pass ? 4 : 0;
      const int jcnt  = pass ? (nct - 4) : 4;
      float acc[2][4][4];
#pragma unroll
      for (int i = 0; i < 2; ++i)
#pragma unroll
        for (int j = 0; j < 4; ++j)
#pragma unroll
          for (int q = 0; q < 4; ++q) acc[i][j][q] = 0.0f;

      // two sections: sec0 = bkp{0,2} with akp{0,2}; sec1 = bkp{1,3} with akp{1,3}
#pragma unroll
      for (int sec = 0; sec < 2; ++sec) {
        uint32_t af0[2][2][4], af1[2][2][4];   // akp=sec, akp=sec+2
#pragma unroll
        for (int i = 0; i < 2; ++i)
#pragma unroll
          for (int s = 0; s < 2; ++s) {
            uint32_t arow = a_base + (uint32_t)(i * 16) * ASTRIDE;
            ldsm_x4(af0[i][s][0], af0[i][s][1], af0[i][s][2], af0[i][s][3],
                    arow + (uint32_t)((sec * 2 + s) * 32));
            ldsm_x4(af1[i][s][0], af1[i][s][1], af1[i][s][2], af1[i][s][3],
                    arow + (uint32_t)(((sec + 2) * 2 + s) * 32));
          }

        uint32_t bfr[4][4];
        // --- bkp = sec (W1h half): mma with af0 (zh) and af1 (zl) ---
#pragma unroll
        for (int j = 0; j < 4; ++j) {
          if (j >= jcnt) break;
          ldsm_x4(bfr[j][0], bfr[j][1], bfr[j][2], bfr[j][3],
                  b_base + (uint32_t)((jbase + j) * 8) * ASTRIDE +
                  (uint32_t)(sec * 64));
        }
#pragma unroll
        for (int j = 0; j < 4; ++j) {
          if (j >= jcnt) break;
#pragma unroll
          for (int i = 0; i < 2; ++i) {
            mma_bf16(acc[i][j][0], acc[i][j][1], acc[i][j][2], acc[i][j][3],
                     af0[i][0][0], af0[i][0][1], af0[i][0][2], af0[i][0][3],
                     bfr[j][0], bfr[j][1]);
            mma_bf16(acc[i][j][0], acc[i][j][1], acc[i][j][2], acc[i][j][3],
                     af0[i][1][0], af0[i][1][1], af0[i][1][2], af0[i][1][3],
                     bfr[j][2], bfr[j][3]);
            mma_bf16(acc[i][j][0], acc[i][j][1], acc[i][j][2], acc[i][j][3],
                     af1[i][0][0], af1[i][0][1], af1[i][0][2], af1[i][0][3],
                     bfr[j][0], bfr[j][1]);
            mma_bf16(acc[i][j][0], acc[i][j][1], acc[i][j][2], acc[i][j][3],
                     af1[i][1][0], af1[i][1][1], af1[i][1][2], af1[i][1][3],
                     bfr[j][2], bfr[j][3]);
          }
        }
        // --- bkp = sec+2 (W1l half): mma with af0 (zh) only ---
#pragma unroll
        for (int j = 0; j < 4; ++j) {
          if (j >= jcnt) break;
          ldsm_x4(bfr[j][0], bfr[j][1], bfr[j][2], bfr[j][3],
                  b_base + (uint32_t)((jbase + j) * 8) * ASTRIDE +
                  (uint32_t)((sec + 2) * 64));
        }
#pragma unroll
        for (int j = 0; j < 4; ++j) {
          if (j >= jcnt) break;
#pragma unroll
          for (int i = 0; i < 2; ++i) {
            mma_bf16(acc[i][j][0], acc[i][j][1], acc[i][j][2], acc[i][j][3],
                     af0[i][0][0], af0[i][0][1], af0[i][0][2], af0[i][0][3],
                     bfr[j][0], bfr[j][1]);
            mma_bf16(acc[i][j][0], acc[i][j][1], acc[i][j][2], acc[i][j][3],
                     af0[i][1][0], af0[i][1][1], af0[i][1][2], af0[i][1][3],
                     bfr[j][2], bfr[j][3]);
          }
        }
      }

      // ---- store this pass (c<100 only), bias added here ----
#pragma unroll
      for (int i = 0; i < 2; ++i) {
        int nrow = n0 + wr * 32 + i * 16 + trow;
        float* p0 = out + (size_t)nrow * 10000u + (unsigned)m * 100u;
#pragma unroll
        for (int j = 0; j < 4; ++j) {
          if (j >= jcnt) break;
          int c = cbase + (jbase + j) * 8 + tcol;
          if (c < K_M) {
            float b0 = bias_s[c], b1 = bias_s[c + 1];
            *(float2*)(p0 + c) =
                make_float2(acc[i][j][0] + b0, acc[i][j][1] + b1);
            *(float2*)(p0 + 8 * 10000u + c) =
                make_float2(acc[i][j][2] + b0, acc[i][j][3] + b1);
          }
        }
      }

      // ---- stage-1(m+1) between the two passes ----
      if (pass == 0 && do_next) {
#pragma unroll
        for (int j = 0; j < 8; ++j)
#pragma unroll
          for (int q = 0; q < 4; ++q) zacc[j][q] = 0.0f;
        stage1_mma(a1_base, b1_base, zacc);
      }
    }
    __syncthreads();   // A' & w0split buffers free for next phase A
  }
}

// ---------------------------------------------------------------------
extern "C" void kernel_launch(void* const* d_in, const int* in_sizes, int n_in,
                              void* d_out, int out_size) {
  const float* x  = (const float*)d_in[0];
  const float* ms = (const float*)d_in[1];
  if (n_in >= 2 && in_sizes[0] == 2306) {
    x  = (const float*)d_in[1];
    ms = (const float*)d_in[0];
  }
  float* out = (float*)d_out;

  setup_kernel<<<(K_LENM * K_M + 255) / 256, 256>>>(ms, out, out_size);

  cudaFuncSetAttribute(pred_kernel,
                       cudaFuncAttributeMaxDynamicSharedMemorySize, SM_TOTAL);
  dim3 grid(K_N / 128, 4);
  pred_kernel<<<grid, 256, SM_TOTAL>>>(x, out);
}

// round 13
// speedup vs baseline: 3.5851x; 1.2405x over previous
#include <cuda_runtime.h>
#include <cuda_bf16.h>
#include <cstdint>
#include <math.h>

// =====================================================================
// NN_Model_19748259627524 — Bayesian NN sampling forward pass.
// Both stages on HMMA (mma.sync bf16), exact-compensated 3-term splits.
// R13: stage-1 output stays in registers as stage-2 A-fragments
// (C-frag == A-frag layout trick). No A' smem, no A STS/LDSM, 1 barrier
// per m. Warps own 16 n-rows x all 100 c.
// =====================================================================

#define JAX_PARTITIONABLE 1

#define K_N     16384
#define K_D     17
#define K_H     64
#define K_M     100
#define K_LENM  1088
#define K_MPRI  65
#define PRED_ELEMS 163840000LL   // 16384*100*100

__device__ float g_w0[K_M * K_LENM];   // [m][i], i = d*64+h
__device__ float g_w1[K_MPRI * K_M];   // [d][c]

// ---------------------------------------------------------------------
// threefry2x32 (JAX rotation schedule)
// ---------------------------------------------------------------------
__device__ __forceinline__ void tf2x32(unsigned k0, unsigned k1,
                                       unsigned x0, unsigned x1,
                                       unsigned &o0, unsigned &o1) {
  unsigned ks2 = k0 ^ k1 ^ 0x1BD11BDAu;
  x0 += k0; x1 += k1;
#define TF_R(r) { x0 += x1; x1 = (x1 << (r)) | (x1 >> (32 - (r))); x1 ^= x0; }
  TF_R(13) TF_R(15) TF_R(26) TF_R(6)  x0 += k1;  x1 += ks2 + 1u;
  TF_R(17) TF_R(29) TF_R(16) TF_R(24) x0 += ks2; x1 += k0 + 2u;
  TF_R(13) TF_R(15) TF_R(26) TF_R(6)  x0 += k0;  x1 += k1 + 3u;
  TF_R(17) TF_R(29) TF_R(16) TF_R(24) x0 += k1;  x1 += ks2 + 4u;
  TF_R(13) TF_R(15) TF_R(26) TF_R(6)  x0 += ks2; x1 += k0 + 5u;
#undef TF_R
  o0 = x0; o1 = x1;
}

__device__ __forceinline__ void get_key(unsigned which, unsigned &s0, unsigned &s1) {
#if JAX_PARTITIONABLE
  tf2x32(0u, 42u, 0u, which, s0, s1);
#else
  unsigned a0, a1, b0, b1;
  tf2x32(0u, 42u, 0u, 2u, a0, a1);
  tf2x32(0u, 42u, 1u, 3u, b0, b1);
  if (which == 0u) { s0 = a0; s1 = b0; } else { s0 = a1; s1 = b1; }
#endif
}

__device__ __forceinline__ float jax_normal(unsigned k0, unsigned k1,
                                            unsigned idx, unsigned half) {
  unsigned a, b, bits;
#if JAX_PARTITIONABLE
  tf2x32(k0, k1, 0u, idx, a, b);
  bits = a ^ b;
#else
  if (idx < half) { tf2x32(k0, k1, idx, idx + half, a, b); bits = a; }
  else            { tf2x32(k0, k1, idx - half, idx, a, b); bits = b; }
#endif
  float u = __uint_as_float((bits >> 9) | 0x3f800000u) - 1.0f;
  float v = fmaf(u, 1.99999994f, -0.99999994f);
  v = fmaxf(v, -0.99999994f);
  return 1.41421356237f * erfinvf(v);
}

// ---------------------------------------------------------------------
// merged setup kernel
// ---------------------------------------------------------------------
__global__ void setup_kernel(const float* __restrict__ ms,
                             float* __restrict__ out, int out_size) {
  int j = blockIdx.x * blockDim.x + threadIdx.x;
  if (j < K_LENM * K_M) {
    unsigned s0, s1; get_key(0u, s0, s1);
    float eps = jax_normal(s0, s1, (unsigned)j, 54400u);
    int i = j / K_M;
    int m = j - i * K_M;
    float vv = fabsf(ms[1153 + i]) + 1e-6f;
    g_w0[m * K_LENM + i] = fmaf(eps, sqrtf(vv), ms[i]);
  }
  if (j < K_MPRI * K_M) {
    unsigned s0, s1; get_key(1u, s0, s1);
    float eps = jax_normal(s0, s1, (unsigned)j, 3250u);
    int d = j / K_M;
    float vv = fabsf(ms[2241 + d]) + 1e-6f;
    g_w1[j] = fmaf(eps, sqrtf(vv), ms[1088 + d]);
  }
  if ((long long)out_size >= PRED_ELEMS + 2306LL) {
    size_t P = (size_t)PRED_ELEMS;
    if (j < 1088) {
      out[P + j]        = ms[j];
      out[P + 1088 + j] = fabsf(ms[1153 + j]) + 1e-6f;
    }
    if (j < 65) {
      out[P + 2176 + j] = ms[1088 + j];
      out[P + 2241 + j] = fabsf(ms[2241 + j]) + 1e-6f;
    }
  }
}

// ---------------------------------------------------------------------
// warp-MMA helpers
// ---------------------------------------------------------------------
__device__ __forceinline__ uint32_t smem_u32(const void* p) {
  uint32_t a;
  asm("{ .reg .u64 t; cvta.to.shared.u64 t, %1; cvt.u32.u64 %0, t; }"
      : "=r"(a) : "l"(p));
  return a;
}

__device__ __forceinline__ void ldsm_x4(uint32_t &r0, uint32_t &r1,
                                        uint32_t &r2, uint32_t &r3,
                                        uint32_t addr) {
  asm volatile("ldmatrix.sync.aligned.m8n8.x4.shared.b16 {%0,%1,%2,%3}, [%4];"
               : "=r"(r0), "=r"(r1), "=r"(r2), "=r"(r3) : "r"(addr));
}

__device__ __forceinline__ void mma_bf16(float &c0, float &c1, float &c2, float &c3,
                                         uint32_t a0, uint32_t a1, uint32_t a2, uint32_t a3,
                                         uint32_t b0, uint32_t b1) {
  asm volatile(
      "mma.sync.aligned.m16n8k16.row.col.f32.bf16.bf16.f32 "
      "{%0,%1,%2,%3}, {%4,%5,%6,%7}, {%8,%9}, {%0,%1,%2,%3};"
      : "+f"(c0), "+f"(c1), "+f"(c2), "+f"(c3)
      : "r"(a0), "r"(a1), "r"(a2), "r"(a3), "r"(b0), "r"(b1));
}

__device__ __forceinline__ uint32_t packbf2(float a, float b) {
  __nv_bfloat162 t;
  t.x = __float2bfloat16(a);
  t.y = __float2bfloat16(b);
  return *(uint32_t*)&t;
}

// ---------------------------------------------------------------------
// smem layout (bytes)
// ---------------------------------------------------------------------
#define ASTRIDE 272        // B' row stride (128 k bf16 + pad)
#define XSTRIDE 144        // xsplit/w0split row stride (64 k bf16 + pad)
#define SM_B    0          // 104*272 = 28288   B' = [W1h|W1l] per c
#define SM_XS   28416      // 128*144 = 18432   xsplit = [xh|xl] per n
#define SM_W0S  46848      // 2 x 64*144 = 18432 (double buffer) [wh|wl] per h
#define SM_BIAS 65280      // 128*4 = 512
#define SM_TOTAL 65792

#define W0SBUF  9216       // 64*144

__global__ void __launch_bounds__(256, 2)
pred_kernel(const float* __restrict__ x, float* __restrict__ out) {
  extern __shared__ char smem[];
  const uint32_t sbase = smem_u32(smem);
  float* bias_s = (float*)(smem + SM_BIAS);

  const int tid  = threadIdx.x;
  const int wid  = tid >> 5;
  const int lane = tid & 31;
  const int n0 = blockIdx.x * 128;
  const int mbase = blockIdx.y * 25;

  // ---- zero xsplit + both w0split buffers (36864 B contiguous) ----
  {
    int4* z = (int4*)(smem + SM_XS);
#pragma unroll
    for (int k = 0; k < 9; ++k) z[tid + k * 256] = make_int4(0, 0, 0, 0);
  }
  __syncthreads();

  // ---- build B' = [W1h | W1l] rows c (104 rows, zero-pad c>=100) ----
  for (int idx = tid; idx < 104 * 32; idx += 256) {
    int c = idx >> 5;
    int h0 = (idx & 31) * 2;
    float v0 = (c < K_M) ? g_w1[(h0 + 1) * K_M + c] : 0.0f;
    float v1 = (c < K_M) ? g_w1[(h0 + 2) * K_M + c] : 0.0f;
    __nv_bfloat162 h2, l2;
    h2.x = __float2bfloat16(v0);
    h2.y = __float2bfloat16(v1);
    l2.x = __float2bfloat16(v0 - __bfloat162float(h2.x));
    l2.y = __float2bfloat16(v1 - __bfloat162float(h2.y));
    char* row = smem + SM_B + c * ASTRIDE;
    *(__nv_bfloat162*)(row + h0 * 2)       = h2;
    *(__nv_bfloat162*)(row + 128 + h0 * 2) = l2;
  }
  if (tid < 128) bias_s[tid] = (tid < K_M) ? g_w1[tid] : 0.0f;

  // ---- build xsplit: [n][k]  xh at d*2, xl at 64+d*2 ----
  for (int idx = tid; idx < 128 * K_D; idx += 256) {
    int n = idx / K_D, d = idx - n * K_D;
    float v = x[(size_t)n0 * K_D + idx];
    __nv_bfloat16 h = __float2bfloat16(v);
    __nv_bfloat16 l = __float2bfloat16(v - __bfloat162float(h));
    char* row = smem + SM_XS + n * XSTRIDE;
    *(__nv_bfloat16*)(row + d * 2)      = h;
    *(__nv_bfloat16*)(row + 64 + d * 2) = l;
  }

  // ---- build w0split(m0) into buf0 ----
  {
    const float* src = g_w0 + (size_t)mbase * K_LENM;
#pragma unroll
    for (int k = 0; k < 5; ++k) {
      int idx = tid + k * 256;
      if (idx < K_LENM) {
        float v = src[idx];
        int d = idx >> 6, h = idx & 63;
        __nv_bfloat16 hi = __float2bfloat16(v);
        __nv_bfloat16 lo = __float2bfloat16(v - __bfloat162float(hi));
        char* row = smem + SM_W0S + h * XSTRIDE;
        *(__nv_bfloat16*)(row + d * 2)      = hi;
        *(__nv_bfloat16*)(row + 64 + d * 2) = lo;
      }
    }
  }
  __syncthreads();

  // ---- hoisted lane bases ----
  const uint32_t a1_base = sbase + SM_XS +
      (uint32_t)((wid * 16 + (lane & 15)) * XSTRIDE + ((lane >> 4) * 8) * 2);
  const uint32_t b1_off = (uint32_t)((lane & 7) * XSTRIDE + ((lane >> 3) * 8) * 2);
  const uint32_t b_base = sbase + SM_B +
      (uint32_t)((lane & 7) * ASTRIDE + ((lane >> 3) * 8) * 2);

  const int trow = lane >> 2;
  const int tcol = (lane & 3) * 2;

  // x fragments (m-invariant): xa[0]=xh ksteps, xa[1]=xl ksteps
  uint32_t xa[2][2][4];
#pragma unroll
  for (int ap = 0; ap < 2; ++ap)
#pragma unroll
    for (int s = 0; s < 2; ++s)
      ldsm_x4(xa[ap][s][0], xa[ap][s][1], xa[ap][s][2], xa[ap][s][3],
              a1_base + (uint32_t)((ap * 2 + s) * 32));

  // per-thread bias (m-invariant): 13 c-tiles
  float2 biasv[13];
#pragma unroll
  for (int j = 0; j < 13; ++j) {
    int c = j * 8 + tcol;
    biasv[j] = make_float2(bias_s[c], bias_s[c + 1]);
  }

  // prefetch w0(m1)
  float pf[5];
  {
    const float* src = g_w0 + (size_t)(mbase + 1) * K_LENM;
#pragma unroll
    for (int k = 0; k < 5; ++k) {
      int idx = tid + k * 256;
      pf[k] = src[idx < K_LENM ? idx : 0];
    }
  }

  const int nrow = n0 + wid * 16 + trow;
  float* const outp = out + (size_t)nrow * 10000u + (unsigned)mbase * 100u;

#pragma unroll 1
  for (int mi = 0; mi < 25; ++mi) {
    // ======== stage 1: zacc = [xh|xl] @ [wh|wl] (3 terms) ========
    float zacc[8][4];
#pragma unroll
    for (int j = 0; j < 8; ++j)
#pragma unroll
      for (int q = 0; q < 4; ++q) zacc[j][q] = 0.0f;

    {
      const uint32_t wb = sbase + SM_W0S + (uint32_t)((mi & 1) * W0SBUF) + b1_off;
#pragma unroll
      for (int j = 0; j < 8; ++j) {
        uint32_t bh[4], bl[4];
        ldsm_x4(bh[0], bh[1], bh[2], bh[3], wb + (uint32_t)(j * 8 * XSTRIDE));
        ldsm_x4(bl[0], bl[1], bl[2], bl[3], wb + (uint32_t)(j * 8 * XSTRIDE + 64));
        mma_bf16(zacc[j][0], zacc[j][1], zacc[j][2], zacc[j][3],
                 xa[0][0][0], xa[0][0][1], xa[0][0][2], xa[0][0][3], bh[0], bh[1]);
        mma_bf16(zacc[j][0], zacc[j][1], zacc[j][2], zacc[j][3],
                 xa[0][1][0], xa[0][1][1], xa[0][1][2], xa[0][1][3], bh[2], bh[3]);
        mma_bf16(zacc[j][0], zacc[j][1], zacc[j][2], zacc[j][3],
                 xa[1][0][0], xa[1][0][1], xa[1][0][2], xa[1][0][3], bh[0], bh[1]);
        mma_bf16(zacc[j][0], zacc[j][1], zacc[j][2], zacc[j][3],
                 xa[1][1][0], xa[1][1][1], xa[1][1][2], xa[1][1][3], bh[2], bh[3]);
        mma_bf16(zacc[j][0], zacc[j][1], zacc[j][2], zacc[j][3],
                 xa[0][0][0], xa[0][0][1], xa[0][0][2], xa[0][0][3], bl[0], bl[1]);
        mma_bf16(zacc[j][0], zacc[j][1], zacc[j][2], zacc[j][3],
                 xa[0][1][0], xa[0][1][1], xa[0][1][2], xa[0][1][3], bl[2], bl[3]);
      }
    }

    // ======== convert: relu + hi/lo split -> stage-2 A fragments ========
    // C-frag(m16n8) == A-frag(m16n8k16) layout: tile 2ks -> regs 0,1;
    // tile 2ks+1 -> regs 2,3.
    uint32_t ah[4][4], al[4][4];
#pragma unroll
    for (int ks = 0; ks < 4; ++ks) {
#pragma unroll
      for (int hf = 0; hf < 2; ++hf) {
        const int j2 = 2 * ks + hf;
        float z0 = fmaxf(zacc[j2][0], 0.0f);
        float z1 = fmaxf(zacc[j2][1], 0.0f);
        float z2 = fmaxf(zacc[j2][2], 0.0f);
        float z3 = fmaxf(zacc[j2][3], 0.0f);
        __nv_bfloat16 h0 = __float2bfloat16(z0);
        __nv_bfloat16 h1 = __float2bfloat16(z1);
        __nv_bfloat16 h2 = __float2bfloat16(z2);
        __nv_bfloat16 h3 = __float2bfloat16(z3);
        ah[ks][hf * 2 + 0] = packbf2(z0, z1);   // same rounding as h0,h1
        ah[ks][hf * 2 + 1] = packbf2(z2, z3);
        al[ks][hf * 2 + 0] = packbf2(z0 - __bfloat162float(h0),
                                     z1 - __bfloat162float(h1));
        al[ks][hf * 2 + 1] = packbf2(z2 - __bfloat162float(h2),
                                     z3 - __bfloat162float(h3));
      }
    }

    // ======== publish w0split(m+1), prefetch w0(m+2) ========
    if (mi + 1 < 25) {
      char* buf = smem + SM_W0S + ((mi + 1) & 1) * W0SBUF;
#pragma unroll
      for (int k = 0; k < 5; ++k) {
        int idx = tid + k * 256;
        if (idx < K_LENM) {
          float v = pf[k];
          int d = idx >> 6, h = idx & 63;
          __nv_bfloat16 hi = __float2bfloat16(v);
          __nv_bfloat16 lo = __float2bfloat16(v - __bfloat162float(hi));
          char* row = buf + h * XSTRIDE;
          *(__nv_bfloat16*)(row + d * 2)      = hi;
          *(__nv_bfloat16*)(row + 64 + d * 2) = lo;
        }
      }
    }
    if (mi + 2 < 25) {
      const float* src = g_w0 + (size_t)(mbase + mi + 2) * K_LENM;
#pragma unroll
      for (int k = 0; k < 5; ++k) {
        int idx = tid + k * 256;
        pf[k] = src[idx < K_LENM ? idx : 0];
      }
    }

    // ======== stage 2: 13 c-tiles, A from registers ========
    float* const pm = outp + mi * 100;
#pragma unroll
    for (int j = 0; j < 13; ++j) {
      uint32_t bq[4][4];   // sections: k0-31(h), k32-63(h), k64-95(l), k96-127(l)
#pragma unroll
      for (int s = 0; s < 4; ++s)
        ldsm_x4(bq[s][0], bq[s][1], bq[s][2], bq[s][3],
                b_base + (uint32_t)(j * 8 * ASTRIDE + s * 64));

      float a0 = 0.0f, a1 = 0.0f, a2 = 0.0f, a3 = 0.0f;
      // zh * Wh
      mma_bf16(a0, a1, a2, a3, ah[0][0], ah[0][1], ah[0][2], ah[0][3], bq[0][0], bq[0][1]);
      mma_bf16(a0, a1, a2, a3, ah[1][0], ah[1][1], ah[1][2], ah[1][3], bq[0][2], bq[0][3]);
      mma_bf16(a0, a1, a2, a3, ah[2][0], ah[2][1], ah[2][2], ah[2][3], bq[1][0], bq[1][1]);
      mma_bf16(a0, a1, a2, a3, ah[3][0], ah[3][1], ah[3][2], ah[3][3], bq[1][2], bq[1][3]);
      // zl * Wh
      mma_bf16(a0, a1, a2, a3, al[0][0], al[0][1], al[0][2], al[0][3], bq[0][0], bq[0][1]);
      mma_bf16(a0, a1, a2, a3, al[1][0], al[1][1], al[1][2], al[1][3], bq[0][2], bq[0][3]);
      mma_bf16(a0, a1, a2, a3, al[2][0], al[2][1], al[2][2], al[2][3], bq[1][0], bq[1][1]);
      mma_bf16(a0, a1, a2, a3, al[3][0], al[3][1], al[3][2], al[3][3], bq[1][2], bq[1][3]);
      // zh * Wl
      mma_bf16(a0, a1, a2, a3, ah[0][0], ah[0][1], ah[0][2], ah[0][3], bq[2][0], bq[2][1]);
      mma_bf16(a0, a1, a2, a3, ah[1][0], ah[1][1], ah[1][2], ah[1][3], bq[2][2], bq[2][3]);
      mma_bf16(a0, a1, a2, a3, ah[2][0], ah[2][1], ah[2][2], ah[2][3], bq[3][0], bq[3][1]);
      mma_bf16(a0, a1, a2, a3, ah[3][0], ah[3][1], ah[3][2], ah[3][3], bq[3][2], bq[3][3]);

      const int c = j * 8 + tcol;
      if (c < K_M) {
        *(float2*)(pm + c) = make_float2(a0 + biasv[j].x, a1 + biasv[j].y);
        *(float2*)(pm + 8 * 10000u + c) =
            make_float2(a2 + biasv[j].x, a3 + biasv[j].y);
      }
    }

    __syncthreads();   // w0split buffer handoff
  }
}

// ---------------------------------------------------------------------
extern "C" void kernel_launch(void* const* d_in, const int* in_sizes, int n_in,
                              void* d_out, int out_size) {
  const float* x  = (const float*)d_in[0];
  const float* ms = (const float*)d_in[1];
  if (n_in >= 2 && in_sizes[0] == 2306) {
    x  = (const float*)d_in[1];
    ms = (const float*)d_in[0];
  }
  float* out = (float*)d_out;

  setup_kernel<<<(K_LENM * K_M + 255) / 256, 256>>>(ms, out, out_size);

  cudaFuncSetAttribute(pred_kernel,
                       cudaFuncAttributeMaxDynamicSharedMemorySize, SM_TOTAL);
  dim3 grid(K_N / 128, 4);
  pred_kernel<<<grid, 256, SM_TOTAL>>>(x, out);
}